// round 1
// baseline (speedup 1.0000x reference)
#include <cuda_runtime.h>
#include <math_constants.h>

// ---------------- problem constants ----------------
constexpr int B_   = 16;
constexpr int NH   = 8;
constexpr int NQ   = 1569;   // 8*14*14 + 1
constexpr int NKV  = 393;    // 8*7*7 + 1
constexpr int HDc  = 96;
constexpr int DIMc = 768;
constexpr int LQ   = 1568;
constexpr int MROWS = B_ * NQ;     // 25104

// ---------------- scratch (device globals; no allocs allowed) ----------------
__device__ float g_q [B_*NH*NQ*HDc];
__device__ float g_k [B_*NH*NQ*HDc];
__device__ float g_v [B_*NH*NQ*HDc];
__device__ float g_qp[B_*NH*NQ*HDc];
__device__ float g_kp[B_*NH*NKV*HDc];
__device__ float g_vp[B_*NH*NKV*HDc];
__device__ float g_E [B_*NH*LQ*22];
__device__ float g_ao[B_*NQ*DIMc];

__device__ __forceinline__ float4 ld4(const float* p){ return *reinterpret_cast<const float4*>(p); }

// ============================================================
// GEMM 1: qkv = x @ qkv_w + qkv_b, scatter into q/k/v [B,H,N,HD]
// 128x64x16 tile, 256 threads, 8x4 micro-tile
// ============================================================
__global__ __launch_bounds__(256) void gemm_qkv_kernel(
    const float* __restrict__ A, const float* __restrict__ Bw, const float* __restrict__ bias)
{
    __shared__ float As[16][128];
    __shared__ float Bs[16][64];
    const int n0 = blockIdx.x * 64;
    const int m0 = blockIdx.y * 128;
    const int t  = threadIdx.x;
    const int tr = t >> 4, tc = t & 15;
    const int ar = t >> 2, ak4 = (t & 3) * 4;
    const int br = t >> 4, bc4 = (t & 15) * 4;

    float acc[8][4];
#pragma unroll
    for (int i = 0; i < 8; i++)
#pragma unroll
        for (int j = 0; j < 4; j++) acc[i][j] = 0.f;

    for (int k0 = 0; k0 < 768; k0 += 16) {
#pragma unroll
        for (int hf = 0; hf < 2; hf++) {
            int row = ar + hf * 64;
            int mm  = m0 + row;
            float4 v = (mm < MROWS) ? ld4(A + (size_t)mm * 768 + k0 + ak4)
                                    : make_float4(0.f,0.f,0.f,0.f);
            As[ak4+0][row] = v.x; As[ak4+1][row] = v.y;
            As[ak4+2][row] = v.z; As[ak4+3][row] = v.w;
        }
        *(float4*)&Bs[br][bc4] = ld4(Bw + (size_t)(k0 + br) * 2304 + n0 + bc4);
        __syncthreads();
#pragma unroll
        for (int kk = 0; kk < 16; kk++) {
            float4 a0 = *(float4*)&As[kk][tr*8];
            float4 a1 = *(float4*)&As[kk][tr*8+4];
            float4 b0 = *(float4*)&Bs[kk][tc*4];
            float ax[8] = {a0.x,a0.y,a0.z,a0.w,a1.x,a1.y,a1.z,a1.w};
#pragma unroll
            for (int i = 0; i < 8; i++) {
                acc[i][0] += ax[i]*b0.x; acc[i][1] += ax[i]*b0.y;
                acc[i][2] += ax[i]*b0.z; acc[i][3] += ax[i]*b0.w;
            }
        }
        __syncthreads();
    }

    const int j0   = n0 + tc * 4;
    const int qkvi = j0 / 768;
    const int head = (j0 % 768) / 96;
    const int c    = j0 % 96;
    float* dst = (qkvi == 0) ? g_q : (qkvi == 1) ? g_k : g_v;
    float4 bv = ld4(bias + j0);
#pragma unroll
    for (int i = 0; i < 8; i++) {
        int mm = m0 + tr * 8 + i;
        if (mm >= MROWS) break;
        int b_ = mm / 1569, n = mm - b_ * 1569;
        float4 rv = make_float4(acc[i][0]+bv.x, acc[i][1]+bv.y, acc[i][2]+bv.z, acc[i][3]+bv.w);
        *(float4*)&dst[(((size_t)b_*8 + head)*1569 + n)*96 + c] = rv;
    }
}

// ============================================================
// GEMM 2: out = g_ao @ proj_w + proj_b
// ============================================================
__global__ __launch_bounds__(256) void gemm_proj_kernel(
    const float* __restrict__ Bw, const float* __restrict__ bias, float* __restrict__ C)
{
    __shared__ float As[16][128];
    __shared__ float Bs[16][64];
    const int n0 = blockIdx.x * 64;
    const int m0 = blockIdx.y * 128;
    const int t  = threadIdx.x;
    const int tr = t >> 4, tc = t & 15;
    const int ar = t >> 2, ak4 = (t & 3) * 4;
    const int br = t >> 4, bc4 = (t & 15) * 4;
    const float* A = g_ao;

    float acc[8][4];
#pragma unroll
    for (int i = 0; i < 8; i++)
#pragma unroll
        for (int j = 0; j < 4; j++) acc[i][j] = 0.f;

    for (int k0 = 0; k0 < 768; k0 += 16) {
#pragma unroll
        for (int hf = 0; hf < 2; hf++) {
            int row = ar + hf * 64;
            int mm  = m0 + row;
            float4 v = (mm < MROWS) ? ld4(A + (size_t)mm * 768 + k0 + ak4)
                                    : make_float4(0.f,0.f,0.f,0.f);
            As[ak4+0][row] = v.x; As[ak4+1][row] = v.y;
            As[ak4+2][row] = v.z; As[ak4+3][row] = v.w;
        }
        *(float4*)&Bs[br][bc4] = ld4(Bw + (size_t)(k0 + br) * 768 + n0 + bc4);
        __syncthreads();
#pragma unroll
        for (int kk = 0; kk < 16; kk++) {
            float4 a0 = *(float4*)&As[kk][tr*8];
            float4 a1 = *(float4*)&As[kk][tr*8+4];
            float4 b0 = *(float4*)&Bs[kk][tc*4];
            float ax[8] = {a0.x,a0.y,a0.z,a0.w,a1.x,a1.y,a1.z,a1.w};
#pragma unroll
            for (int i = 0; i < 8; i++) {
                acc[i][0] += ax[i]*b0.x; acc[i][1] += ax[i]*b0.y;
                acc[i][2] += ax[i]*b0.z; acc[i][3] += ax[i]*b0.w;
            }
        }
        __syncthreads();
    }

    const int j0 = n0 + tc * 4;
    float4 bv = ld4(bias + j0);
#pragma unroll
    for (int i = 0; i < 8; i++) {
        int mm = m0 + tr * 8 + i;
        if (mm >= MROWS) break;
        float4 rv = make_float4(acc[i][0]+bv.x, acc[i][1]+bv.y, acc[i][2]+bv.z, acc[i][3]+bv.w);
        *(float4*)&C[(size_t)mm*768 + j0] = rv;
    }
}

// ============================================================
// Attention pool (depthwise conv3d 3x3x3 + zero pad) + LayerNorm
// sel: 0 -> q (stride 1, out 14x14), 1 -> k, 2 -> v (stride 2, out 7x7)
// block: 96 threads (one per channel), 8 tokens per block
// ============================================================
__global__ __launch_bounds__(96) void pool_ln_kernel(
    const float* __restrict__ w, const float* __restrict__ gamma, const float* __restrict__ beta,
    int sel, int outH, int outW, int stride, int Nout)
{
    const int bh = blockIdx.x;
    const int c  = threadIdx.x;
    const int lane = c & 31, wid = c >> 5;
    const float* in  = (sel == 0) ? g_q : (sel == 1) ? g_k : g_v;
    float*       out = (sel == 0) ? g_qp : (sel == 1) ? g_kp : g_vp;
    const float* inb  = in  + (size_t)bh * NQ * 96;
    float*       outb = out + (size_t)bh * Nout * 96;

    float wr[27];
#pragma unroll
    for (int i = 0; i < 27; i++) wr[i] = w[c * 27 + i];
    const float gg = gamma[c], bb = beta[c];
    __shared__ float rs[3], rq[3];
    const int HW = outH * outW;

    for (int i = 0; i < 8; i++) {
        int p = blockIdx.y * 8 + i;
        if (p >= Nout) break;
        float val;
        if (p == 0) {
            val = inb[c];
        } else {
            int idx = p - 1;
            int ot = idx / HW, r = idx - ot * HW;
            int oh = r / outW, ow = r - oh * outW;
            val = 0.f;
#pragma unroll
            for (int dt = 0; dt < 3; dt++) {
                int it = ot + dt - 1;
                if ((unsigned)it >= 8u) continue;
#pragma unroll
                for (int dh = 0; dh < 3; dh++) {
                    int ih = oh * stride + dh - 1;
                    if ((unsigned)ih >= 14u) continue;
#pragma unroll
                    for (int dw = 0; dw < 3; dw++) {
                        int iw = ow * stride + dw - 1;
                        if ((unsigned)iw >= 14u) continue;
                        val += inb[(size_t)(1 + (it*14 + ih)*14 + iw)*96 + c] * wr[dt*9 + dh*3 + dw];
                    }
                }
            }
        }
        float s1 = val, s2 = val * val;
#pragma unroll
        for (int off = 16; off; off >>= 1) {
            s1 += __shfl_xor_sync(0xffffffffu, s1, off);
            s2 += __shfl_xor_sync(0xffffffffu, s2, off);
        }
        if (lane == 0) { rs[wid] = s1; rq[wid] = s2; }
        __syncthreads();
        float ts = rs[0] + rs[1] + rs[2];
        float tq = rq[0] + rq[1] + rq[2];
        __syncthreads();
        float mean = ts * (1.f / 96.f);
        float var  = tq * (1.f / 96.f) - mean * mean;
        outb[(size_t)p * 96 + c] = (val - mean) * rsqrtf(var + 1e-5f) * gg + bb;
    }
}

// ============================================================
// Rel-pos bias decomposition: E[bh, p, 0:7]=q.Rh, [7:14]=q.Rw, [14:22]=q.Rt
// warp per body query
// ============================================================
__global__ __launch_bounds__(256) void ebias_kernel(
    const float* __restrict__ rh, const float* __restrict__ rw, const float* __restrict__ rt)
{
    const int bh   = blockIdx.x;
    const int warp = threadIdx.x >> 5, lane = threadIdx.x & 31;
    const int p = blockIdx.y * 8 + warp;
    if (p >= LQ) return;
    const float* q = g_qp + ((size_t)bh * NQ + 1 + p) * 96;
    const float q0 = q[lane], q1 = q[lane + 32], q2 = q[lane + 64];
    const int t = p / 196, r = p - t * 196;
    const int hh = r / 14, ww = r - hh * 14;
    float* Eo = g_E + ((size_t)bh * LQ + p) * 22;

#pragma unroll
    for (int kh = 0; kh < 7; kh++) {
        const float* rr = rh + (hh - 2*kh + 12) * 96;
        float s = q0*rr[lane] + q1*rr[lane+32] + q2*rr[lane+64];
#pragma unroll
        for (int off = 16; off; off >>= 1) s += __shfl_xor_sync(0xffffffffu, s, off);
        if (lane == 0) Eo[kh] = s;
    }
#pragma unroll
    for (int kw = 0; kw < 7; kw++) {
        const float* rr = rw + (ww - 2*kw + 12) * 96;
        float s = q0*rr[lane] + q1*rr[lane+32] + q2*rr[lane+64];
#pragma unroll
        for (int off = 16; off; off >>= 1) s += __shfl_xor_sync(0xffffffffu, s, off);
        if (lane == 0) Eo[7 + kw] = s;
    }
#pragma unroll
    for (int kt = 0; kt < 8; kt++) {
        const float* rr = rt + (t - kt + 7) * 96;
        float s = q0*rr[lane] + q1*rr[lane+32] + q2*rr[lane+64];
#pragma unroll
        for (int off = 16; off; off >>= 1) s += __shfl_xor_sync(0xffffffffu, s, off);
        if (lane == 0) Eo[14 + kt] = s;
    }
}

// ============================================================
// Fused attention: scores + rel bias + online softmax + AV + residual
// block: 256 threads, 32 queries; K/V streamed in 64-key tiles through
// one reused smem buffer (static smem < 48KB).
// thread t: queries {t/16, t/16+16}, key lane / channel group = t%16
// ============================================================
__global__ __launch_bounds__(256) void attn_kernel()
{
    __shared__ float qs[32 * 96];
    __shared__ float kv[64 * 100];   // padded pitch 100 -> conflict-free f4
    __shared__ float Ps[32 * 64];
    __shared__ float Eb[32 * 22];

    const int bh = blockIdx.y, b = bh >> 3, h = bh & 7;
    const int q0 = blockIdx.x * 32;
    const int t  = threadIdx.x;
    const int tq = t >> 4, tk = t & 15;
    const float scale = 0.10206207261596577f;  // 96^-0.5

    const float* qbase = g_qp + (size_t)bh * NQ * 96;
    const float* kbase = g_kp + (size_t)bh * NKV * 96;
    const float* vbase = g_vp + (size_t)bh * NKV * 96;

    // load Q tile (pre-scaled)
    for (int i = t; i < 32 * 24; i += 256) {
        int q = i / 24, c4 = i - q * 24;
        int qg = q0 + q;
        float4 v = make_float4(0.f,0.f,0.f,0.f);
        if (qg < NQ) v = ld4(qbase + (size_t)qg * 96 + c4 * 4);
        v.x *= scale; v.y *= scale; v.z *= scale; v.w *= scale;
        *(float4*)&qs[q * 96 + c4 * 4] = v;
    }
    // load per-query bias terms
    for (int i = t; i < 32 * 22; i += 256) {
        int q = i / 22, e = i - q * 22;
        int qg = q0 + q;
        Eb[i] = (qg >= 1 && qg < NQ) ? g_E[((size_t)bh * LQ + (qg - 1)) * 22 + e] : 0.f;
    }

    float m0v = -CUDART_INF_F, m1v = -CUDART_INF_F, l0 = 0.f, l1 = 0.f;
    float acc0[6] = {0,0,0,0,0,0}, acc1[6] = {0,0,0,0,0,0};
    const int qg0 = q0 + tq, qg1 = q0 + tq + 16;

    for (int k0 = 0; k0 < NKV; k0 += 64) {
        const int nv = min(64, NKV - k0);
        __syncthreads();   // prev AV done with kv
        for (int i = t; i < 64 * 24; i += 256) {
            int r = i / 24, c4 = i - r * 24;
            float4 v = (r < nv) ? ld4(kbase + (size_t)(k0 + r) * 96 + c4 * 4)
                                : make_float4(0.f,0.f,0.f,0.f);
            *(float4*)&kv[r * 100 + c4 * 4] = v;
        }
        __syncthreads();

        float s0[4] = {0,0,0,0}, s1[4] = {0,0,0,0};
#pragma unroll 4
        for (int c4 = 0; c4 < 24; c4++) {
            float4 a0 = *(float4*)&qs[tq * 96 + c4 * 4];
            float4 a1 = *(float4*)&qs[(tq + 16) * 96 + c4 * 4];
#pragma unroll
            for (int j = 0; j < 4; j++) {
                float4 bb = *(float4*)&kv[(tk + 16*j) * 100 + c4 * 4];
                s0[j] += a0.x*bb.x + a0.y*bb.y + a0.z*bb.z + a0.w*bb.w;
                s1[j] += a1.x*bb.x + a1.y*bb.y + a1.z*bb.z + a1.w*bb.w;
            }
        }
        // bias + mask
#pragma unroll
        for (int j = 0; j < 4; j++) {
            int g = k0 + tk + 16 * j;
            if (g >= NKV) { s0[j] = -CUDART_INF_F; s1[j] = -CUDART_INF_F; }
            else if (g > 0) {
                int kb = g - 1;
                int kt_ = kb / 49, r2 = kb - kt_ * 49;
                int kh_ = r2 / 7,  kw_ = r2 - kh_ * 7;
                if (qg0 > 0) s0[j] += Eb[tq*22 + kh_] + Eb[tq*22 + 7 + kw_] + Eb[tq*22 + 14 + kt_];
                if (qg1 > 0) s1[j] += Eb[(tq+16)*22 + kh_] + Eb[(tq+16)*22 + 7 + kw_] + Eb[(tq+16)*22 + 14 + kt_];
            }
        }
        // online softmax, query row 0 (tq)
        {
            float mt = fmaxf(fmaxf(s0[0], s0[1]), fmaxf(s0[2], s0[3]));
#pragma unroll
            for (int off = 8; off; off >>= 1) mt = fmaxf(mt, __shfl_xor_sync(0xffffffffu, mt, off));
            float mn = fmaxf(m0v, mt);
            float alpha = __expf(m0v - mn);
            m0v = mn;
            float ls = 0.f;
#pragma unroll
            for (int j = 0; j < 4; j++) {
                float p = __expf(s0[j] - mn);
                ls += p;
                Ps[tq * 64 + tk + 16 * j] = p;
            }
#pragma unroll
            for (int off = 8; off; off >>= 1) ls += __shfl_xor_sync(0xffffffffu, ls, off);
            l0 = l0 * alpha + ls;
#pragma unroll
            for (int i = 0; i < 6; i++) acc0[i] *= alpha;
        }
        // online softmax, query row 1 (tq+16)
        {
            float mt = fmaxf(fmaxf(s1[0], s1[1]), fmaxf(s1[2], s1[3]));
#pragma unroll
            for (int off = 8; off; off >>= 1) mt = fmaxf(mt, __shfl_xor_sync(0xffffffffu, mt, off));
            float mn = fmaxf(m1v, mt);
            float alpha = __expf(m1v - mn);
            m1v = mn;
            float ls = 0.f;
#pragma unroll
            for (int j = 0; j < 4; j++) {
                float p = __expf(s1[j] - mn);
                ls += p;
                Ps[(tq + 16) * 64 + tk + 16 * j] = p;
            }
#pragma unroll
            for (int off = 8; off; off >>= 1) ls += __shfl_xor_sync(0xffffffffu, ls, off);
            l1 = l1 * alpha + ls;
#pragma unroll
            for (int i = 0; i < 6; i++) acc1[i] *= alpha;
        }
        __syncthreads();   // scores done reading kv(K); Ps visible
        // load V into the same buffer
        for (int i = t; i < 64 * 24; i += 256) {
            int r = i / 24, c4 = i - r * 24;
            float4 v = (r < nv) ? ld4(vbase + (size_t)(k0 + r) * 96 + c4 * 4)
                                : make_float4(0.f,0.f,0.f,0.f);
            *(float4*)&kv[r * 100 + c4 * 4] = v;
        }
        __syncthreads();
        // AV: thread owns channels [tk*6, tk*6+6)
#pragma unroll 4
        for (int k = 0; k < 64; k++) {
            float p0 = Ps[tq * 64 + k];
            float p1 = Ps[(tq + 16) * 64 + k];
            const float2* vr = (const float2*)&kv[k * 100 + tk * 6];
#pragma unroll
            for (int i2 = 0; i2 < 3; i2++) {
                float2 vv = vr[i2];
                acc0[2*i2]   += p0 * vv.x; acc0[2*i2+1] += p0 * vv.y;
                acc1[2*i2]   += p1 * vv.x; acc1[2*i2+1] += p1 * vv.y;
            }
        }
    }

    // epilogue: out/l + residual, write transposed [B, N, H*HD]
    if (qg0 < NQ) {
        float inv = 1.f / l0;
#pragma unroll
        for (int i = 0; i < 6; i++) {
            int c = tk * 6 + i;
            float val = acc0[i] * inv;
            if (qg0 > 0) val += qbase[(size_t)qg0 * 96 + c];
            g_ao[((size_t)b * NQ + qg0) * 768 + h * 96 + c] = val;
        }
    }
    if (qg1 < NQ) {
        float inv = 1.f / l1;
#pragma unroll
        for (int i = 0; i < 6; i++) {
            int c = tk * 6 + i;
            float val = acc1[i] * inv;
            if (qg1 > 0) val += qbase[(size_t)qg1 * 96 + c];
            g_ao[((size_t)b * NQ + qg1) * 768 + h * 96 + c] = val;
        }
    }
}

// ============================================================
// launch
// ============================================================
extern "C" void kernel_launch(void* const* d_in, const int* in_sizes, int n_in,
                              void* d_out, int out_size)
{
    const float* x      = (const float*)d_in[0];
    const float* qkv_w  = (const float*)d_in[1];
    const float* qkv_b  = (const float*)d_in[2];
    const float* pw_q   = (const float*)d_in[3];
    const float* pw_k   = (const float*)d_in[4];
    const float* pw_v   = (const float*)d_in[5];
    const float* lnq_g  = (const float*)d_in[6];
    const float* lnq_b  = (const float*)d_in[7];
    const float* lnk_g  = (const float*)d_in[8];
    const float* lnk_b  = (const float*)d_in[9];
    const float* lnv_g  = (const float*)d_in[10];
    const float* lnv_b  = (const float*)d_in[11];
    const float* rel_h  = (const float*)d_in[12];
    const float* rel_w  = (const float*)d_in[13];
    const float* rel_t  = (const float*)d_in[14];
    const float* proj_w = (const float*)d_in[15];
    const float* proj_b = (const float*)d_in[16];
    float* out = (float*)d_out;

    // 1. fused QKV projection, scattered to [B,H,N,HD]
    gemm_qkv_kernel<<<dim3(36, 197), 256>>>(x, qkv_w, qkv_b);
    // 2. attention pooling + LN
    pool_ln_kernel<<<dim3(128, 197), 96>>>(pw_q, lnq_g, lnq_b, 0, 14, 14, 1, 1569);
    pool_ln_kernel<<<dim3(128, 50),  96>>>(pw_k, lnk_g, lnk_b, 1, 7, 7, 2, 393);
    pool_ln_kernel<<<dim3(128, 50),  96>>>(pw_v, lnv_g, lnv_b, 2, 7, 7, 2, 393);
    // 3. decomposed rel-pos bias terms
    ebias_kernel<<<dim3(128, 196), 256>>>(rel_h, rel_w, rel_t);
    // 4. fused attention (bias + softmax + AV + residual, transposed output)
    attn_kernel<<<dim3(50, 128), 256>>>();
    // 5. output projection
    gemm_proj_kernel<<<dim3(12, 197), 256>>>(proj_w, proj_b, out);
}

// round 5
// speedup vs baseline: 1.7084x; 1.7084x over previous
#include <cuda_runtime.h>
#include <cuda_fp16.h>
#include <cstdint>
#include <math_constants.h>

// ---------------- problem constants ----------------
constexpr int B_   = 16;
constexpr int NH   = 8;
constexpr int NQ   = 1569;   // 8*14*14 + 1
constexpr int NKV  = 393;    // 8*7*7 + 1
constexpr int HDc  = 96;
constexpr int DIMc = 768;
constexpr int LQ   = 1568;
constexpr int MROWS = B_ * NQ;     // 25104

// ---------------- scratch (device globals; no allocs allowed) ----------------
__device__ float g_q [B_*NH*NQ*HDc];
__device__ float g_k [B_*NH*NQ*HDc];
__device__ float g_v [B_*NH*NQ*HDc];
__device__ float g_qp[B_*NH*NQ*HDc];
__device__ float g_kp[B_*NH*NKV*HDc];
__device__ float g_vp[B_*NH*NKV*HDc];
__device__ float g_E [B_*NH*LQ*22];
__device__ __half g_x16 [MROWS*DIMc];
__device__ __half g_w1T [3*DIMc*DIMc];   // qkv_w transposed [2304][768]
__device__ __half g_w2T [DIMc*DIMc];     // proj_w transposed [768][768]
__device__ __half g_ao16[MROWS*DIMc];

__device__ __forceinline__ float4 ld4(const float* p){ return *reinterpret_cast<const float4*>(p); }

// ---------------- tensor-core helpers ----------------
__device__ __forceinline__ void ldsm4(unsigned int &r0, unsigned int &r1,
                                      unsigned int &r2, unsigned int &r3,
                                      const __half* p)
{
    unsigned int a = (unsigned int)__cvta_generic_to_shared(p);
    asm volatile("ldmatrix.sync.aligned.m8n8.x4.shared.b16 {%0,%1,%2,%3}, [%4];"
                 : "=r"(r0), "=r"(r1), "=r"(r2), "=r"(r3) : "r"(a));
}
__device__ __forceinline__ void mma16816(float* d, const unsigned int* a, const unsigned int* b)
{
    asm volatile("mma.sync.aligned.m16n8k16.row.col.f32.f16.f16.f32 "
                 "{%0,%1,%2,%3}, {%4,%5,%6,%7}, {%8,%9}, {%0,%1,%2,%3};"
                 : "+f"(d[0]), "+f"(d[1]), "+f"(d[2]), "+f"(d[3])
                 : "r"(a[0]), "r"(a[1]), "r"(a[2]), "r"(a[3]), "r"(b[0]), "r"(b[1]));
}

// ---------------- conversion kernels (write device globals directly) ----------
__global__ __launch_bounds__(256) void conv_x_kernel(const float* __restrict__ x, int n4)
{
    int i = blockIdx.x * 256 + threadIdx.x;
    if (i >= n4) return;
    float4 v = reinterpret_cast<const float4*>(x)[i];
    reinterpret_cast<__half2*>(g_x16)[2*i]   = __floats2half2_rn(v.x, v.y);
    reinterpret_cast<__half2*>(g_x16)[2*i+1] = __floats2half2_rn(v.z, v.w);
}

// w[K=768][N] fp32 -> wt[N][768] fp16 ; which: 0 -> g_w1T, 1 -> g_w2T
__global__ __launch_bounds__(256) void convT_kernel(const float* __restrict__ w, int N, int which)
{
    __shared__ float tile[32][33];
    __half* wt = which ? g_w2T : g_w1T;
    int n0 = blockIdx.x * 32, k0 = blockIdx.y * 32;
    int tx = threadIdx.x, ty = threadIdx.y;
#pragma unroll
    for (int i = 0; i < 32; i += 8)
        tile[ty + i][tx] = w[(size_t)(k0 + ty + i) * N + n0 + tx];
    __syncthreads();
#pragma unroll
    for (int i = 0; i < 32; i += 8)
        wt[(size_t)(n0 + ty + i) * 768 + k0 + tx] = __float2half(tile[tx][ty + i]);
}

// ============================================================
// fp16 tensor-core GEMM body: C[M,N] = A[M,768] @ BT[N,768]^T + bias
// CTA 128x128, K-tile 32, 8 warps (4x2), warp tile 32x64.
// MODE 0: A=g_x16, BT=g_w1T, scatter into g_q/g_k/g_v fp32 [B,H,N,HD]
// MODE 1: A=g_ao16, BT=g_w2T, plain fp32 C write
// ============================================================
template<int MODE>
__device__ __forceinline__ void gemm16_body(const float* __restrict__ bias, float* __restrict__ C)
{
    __shared__ __half As[2][128*40];
    __shared__ __half Bs[2][128*40];
    const __half* A  = (MODE == 0) ? g_x16 : g_ao16;
    const __half* BT = (MODE == 0) ? g_w1T : g_w2T;
    const int t = threadIdx.x;
    const int n0 = blockIdx.x * 128, m0 = blockIdx.y * 128;
    const int w = t >> 5, lane = t & 31;
    const int wr = w >> 1, wc = w & 1;
    const int arow = t >> 1, aseg = t & 1;

    const __half* Ag = A + (size_t)min(m0 + arow, MROWS - 1) * 768 + aseg * 16;
    const __half* Bg = BT + (size_t)(n0 + arow) * 768 + aseg * 16;

    const int a_m = (lane & 7) + ((lane >> 3) & 1) * 8;
    const int a_k = ((lane >> 4) & 1) * 8;
    const int b_n = (lane & 7) + ((lane >> 4) & 1) * 8;
    const int b_k = ((lane >> 3) & 1) * 8;

    uint4 ra0 = *(const uint4*)Ag;
    uint4 ra1 = *(const uint4*)(Ag + 8);
    uint4 rb0 = *(const uint4*)Bg;
    uint4 rb1 = *(const uint4*)(Bg + 8);
    {
        __half* Ad = &As[0][0] + arow * 40 + aseg * 16;
        *(uint4*)Ad = ra0; *(uint4*)(Ad + 8) = ra1;
        __half* Bd = &Bs[0][0] + arow * 40 + aseg * 16;
        *(uint4*)Bd = rb0; *(uint4*)(Bd + 8) = rb1;
    }
    __syncthreads();

    float acc[2][8][4];
#pragma unroll
    for (int i = 0; i < 2; i++)
#pragma unroll
        for (int j = 0; j < 8; j++)
#pragma unroll
            for (int r = 0; r < 4; r++) acc[i][j][r] = 0.f;

    for (int kt = 0; kt < 24; kt++) {
        const int cur = kt & 1;
        if (kt < 23) {
            const __half* Ap = Ag + (kt + 1) * 32;
            ra0 = *(const uint4*)Ap; ra1 = *(const uint4*)(Ap + 8);
            const __half* Bp = Bg + (kt + 1) * 32;
            rb0 = *(const uint4*)Bp; rb1 = *(const uint4*)(Bp + 8);
        }
        const __half* Ab = &As[cur][0];
        const __half* Bb = &Bs[cur][0];
#pragma unroll
        for (int kk = 0; kk < 32; kk += 16) {
            unsigned int af[2][4];
            ldsm4(af[0][0], af[0][1], af[0][2], af[0][3],
                  Ab + (wr*32 + a_m) * 40 + kk + a_k);
            ldsm4(af[1][0], af[1][1], af[1][2], af[1][3],
                  Ab + (wr*32 + 16 + a_m) * 40 + kk + a_k);
            unsigned int bf[8][2];
#pragma unroll
            for (int nf2 = 0; nf2 < 4; nf2++) {
                unsigned int r0, r1, r2, r3;
                ldsm4(r0, r1, r2, r3, Bb + (wc*64 + nf2*16 + b_n) * 40 + kk + b_k);
                bf[2*nf2][0] = r0; bf[2*nf2][1] = r1;
                bf[2*nf2+1][0] = r2; bf[2*nf2+1][1] = r3;
            }
#pragma unroll
            for (int mf = 0; mf < 2; mf++)
#pragma unroll
                for (int nf = 0; nf < 8; nf++)
                    mma16816(acc[mf][nf], af[mf], bf[nf]);
        }
        if (kt < 23) {
            const int nxt = cur ^ 1;
            __half* Ad = &As[nxt][0] + arow * 40 + aseg * 16;
            *(uint4*)Ad = ra0; *(uint4*)(Ad + 8) = ra1;
            __half* Bd = &Bs[nxt][0] + arow * 40 + aseg * 16;
            *(uint4*)Bd = rb0; *(uint4*)(Bd + 8) = rb1;
            __syncthreads();
        }
    }

    const int mbase = m0 + wr * 32 + (lane >> 2);
    const int nbase = n0 + wc * 64 + (lane & 3) * 2;
#pragma unroll
    for (int mf = 0; mf < 2; mf++) {
#pragma unroll
        for (int nf = 0; nf < 8; nf++) {
            const int n = nbase + nf * 8;
            const float2 bv = *(const float2*)&bias[n];
#pragma unroll
            for (int hh = 0; hh < 2; hh++) {
                const int m = mbase + mf * 16 + hh * 8;
                if (m >= MROWS) continue;
                float2 v2;
                v2.x = acc[mf][nf][2*hh]   + bv.x;
                v2.y = acc[mf][nf][2*hh+1] + bv.y;
                if (MODE == 0) {
                    const int qkvi = n / 768, rem = n - qkvi * 768;
                    const int head = rem / 96, c = rem - head * 96;
                    float* dst = (qkvi == 0) ? g_q : (qkvi == 1) ? g_k : g_v;
                    const int b_ = m / 1569, nn = m - b_ * 1569;
                    *(float2*)&dst[(((size_t)b_*8 + head)*1569 + nn)*96 + c] = v2;
                } else {
                    *(float2*)&C[(size_t)m * 768 + n] = v2;
                }
            }
        }
    }
}

__global__ __launch_bounds__(256) void gemm16_qkv_kernel(const float* __restrict__ bias)
{
    gemm16_body<0>(bias, 0);
}

__global__ __launch_bounds__(256) void gemm16_proj_kernel(const float* __restrict__ bias,
                                                          float* __restrict__ C)
{
    gemm16_body<1>(bias, C);
}

// ============================================================
// Attention pool (depthwise conv3d 3x3x3 + zero pad) + LayerNorm
// ============================================================
__global__ __launch_bounds__(96) void pool_ln_kernel(
    const float* __restrict__ w, const float* __restrict__ gamma, const float* __restrict__ beta,
    int sel, int outH, int outW, int stride, int Nout)
{
    const int bh = blockIdx.x;
    const int c  = threadIdx.x;
    const int lane = c & 31, wid = c >> 5;
    const float* in  = (sel == 0) ? g_q : (sel == 1) ? g_k : g_v;
    float*       out = (sel == 0) ? g_qp : (sel == 1) ? g_kp : g_vp;
    const float* inb  = in  + (size_t)bh * NQ * 96;
    float*       outb = out + (size_t)bh * Nout * 96;

    float wr[27];
#pragma unroll
    for (int i = 0; i < 27; i++) wr[i] = w[c * 27 + i];
    const float gg = gamma[c], bb = beta[c];
    __shared__ float rs[3], rq[3];
    const int HW = outH * outW;

    for (int i = 0; i < 8; i++) {
        int p = blockIdx.y * 8 + i;
        if (p >= Nout) break;
        float val;
        if (p == 0) {
            val = inb[c];
        } else {
            int idx = p - 1;
            int ot = idx / HW, r = idx - ot * HW;
            int oh = r / outW, ow = r - oh * outW;
            val = 0.f;
#pragma unroll
            for (int dt = 0; dt < 3; dt++) {
                int it = ot + dt - 1;
                if ((unsigned)it >= 8u) continue;
#pragma unroll
                for (int dh = 0; dh < 3; dh++) {
                    int ih = oh * stride + dh - 1;
                    if ((unsigned)ih >= 14u) continue;
#pragma unroll
                    for (int dw = 0; dw < 3; dw++) {
                        int iw = ow * stride + dw - 1;
                        if ((unsigned)iw >= 14u) continue;
                        val += inb[(size_t)(1 + (it*14 + ih)*14 + iw)*96 + c] * wr[dt*9 + dh*3 + dw];
                    }
                }
            }
        }
        float s1 = val, s2 = val * val;
#pragma unroll
        for (int off = 16; off; off >>= 1) {
            s1 += __shfl_xor_sync(0xffffffffu, s1, off);
            s2 += __shfl_xor_sync(0xffffffffu, s2, off);
        }
        if (lane == 0) { rs[wid] = s1; rq[wid] = s2; }
        __syncthreads();
        float ts = rs[0] + rs[1] + rs[2];
        float tq = rq[0] + rq[1] + rq[2];
        __syncthreads();
        float mean = ts * (1.f / 96.f);
        float var  = tq * (1.f / 96.f) - mean * mean;
        outb[(size_t)p * 96 + c] = (val - mean) * rsqrtf(var + 1e-5f) * gg + bb;
    }
}

// ============================================================
// Rel-pos bias decomposition: E[bh, p, 0:7]=q.Rh, [7:14]=q.Rw, [14:22]=q.Rt
// ============================================================
__global__ __launch_bounds__(256) void ebias_kernel(
    const float* __restrict__ rh, const float* __restrict__ rw, const float* __restrict__ rt)
{
    const int bh   = blockIdx.x;
    const int warp = threadIdx.x >> 5, lane = threadIdx.x & 31;
    const int p = blockIdx.y * 8 + warp;
    if (p >= LQ) return;
    const float* q = g_qp + ((size_t)bh * NQ + 1 + p) * 96;
    const float q0 = q[lane], q1 = q[lane + 32], q2 = q[lane + 64];
    const int t = p / 196, r = p - t * 196;
    const int hh = r / 14, ww = r - hh * 14;
    float* Eo = g_E + ((size_t)bh * LQ + p) * 22;

#pragma unroll
    for (int kh = 0; kh < 7; kh++) {
        const float* rr = rh + (hh - 2*kh + 12) * 96;
        float s = q0*rr[lane] + q1*rr[lane+32] + q2*rr[lane+64];
#pragma unroll
        for (int off = 16; off; off >>= 1) s += __shfl_xor_sync(0xffffffffu, s, off);
        if (lane == 0) Eo[kh] = s;
    }
#pragma unroll
    for (int kw = 0; kw < 7; kw++) {
        const float* rr = rw + (ww - 2*kw + 12) * 96;
        float s = q0*rr[lane] + q1*rr[lane+32] + q2*rr[lane+64];
#pragma unroll
        for (int off = 16; off; off >>= 1) s += __shfl_xor_sync(0xffffffffu, s, off);
        if (lane == 0) Eo[7 + kw] = s;
    }
#pragma unroll
    for (int kt = 0; kt < 8; kt++) {
        const float* rr = rt + (t - kt + 7) * 96;
        float s = q0*rr[lane] + q1*rr[lane+32] + q2*rr[lane+64];
#pragma unroll
        for (int off = 16; off; off >>= 1) s += __shfl_xor_sync(0xffffffffu, s, off);
        if (lane == 0) Eo[14 + kt] = s;
    }
}

// ============================================================
// Fused attention: scores + rel bias + online softmax + AV + residual
// ============================================================
__global__ __launch_bounds__(256) void attn_kernel()
{
    __shared__ float qs[32 * 96];
    __shared__ float kv[64 * 100];
    __shared__ float Ps[32 * 64];
    __shared__ float Eb[32 * 22];

    const int bh = blockIdx.y, b = bh >> 3, h = bh & 7;
    const int q0 = blockIdx.x * 32;
    const int t  = threadIdx.x;
    const int tq = t >> 4, tk = t & 15;
    const float scale = 0.10206207261596577f;  // 96^-0.5

    const float* qbase = g_qp + (size_t)bh * NQ * 96;
    const float* kbase = g_kp + (size_t)bh * NKV * 96;
    const float* vbase = g_vp + (size_t)bh * NKV * 96;

    for (int i = t; i < 32 * 24; i += 256) {
        int q = i / 24, c4 = i - q * 24;
        int qg = q0 + q;
        float4 v = make_float4(0.f,0.f,0.f,0.f);
        if (qg < NQ) v = ld4(qbase + (size_t)qg * 96 + c4 * 4);
        v.x *= scale; v.y *= scale; v.z *= scale; v.w *= scale;
        *(float4*)&qs[q * 96 + c4 * 4] = v;
    }
    for (int i = t; i < 32 * 22; i += 256) {
        int q = i / 22, e = i - q * 22;
        int qg = q0 + q;
        Eb[i] = (qg >= 1 && qg < NQ) ? g_E[((size_t)bh * LQ + (qg - 1)) * 22 + e] : 0.f;
    }

    float m0v = -CUDART_INF_F, m1v = -CUDART_INF_F, l0 = 0.f, l1 = 0.f;
    float acc0[6] = {0,0,0,0,0,0}, acc1[6] = {0,0,0,0,0,0};
    const int qg0 = q0 + tq, qg1 = q0 + tq + 16;

    for (int k0 = 0; k0 < NKV; k0 += 64) {
        const int nv = min(64, NKV - k0);
        __syncthreads();
        for (int i = t; i < 64 * 24; i += 256) {
            int r = i / 24, c4 = i - r * 24;
            float4 v = (r < nv) ? ld4(kbase + (size_t)(k0 + r) * 96 + c4 * 4)
                                : make_float4(0.f,0.f,0.f,0.f);
            *(float4*)&kv[r * 100 + c4 * 4] = v;
        }
        __syncthreads();

        float s0[4] = {0,0,0,0}, s1[4] = {0,0,0,0};
#pragma unroll 4
        for (int c4 = 0; c4 < 24; c4++) {
            float4 a0 = *(float4*)&qs[tq * 96 + c4 * 4];
            float4 a1 = *(float4*)&qs[(tq + 16) * 96 + c4 * 4];
#pragma unroll
            for (int j = 0; j < 4; j++) {
                float4 bb = *(float4*)&kv[(tk + 16*j) * 100 + c4 * 4];
                s0[j] += a0.x*bb.x + a0.y*bb.y + a0.z*bb.z + a0.w*bb.w;
                s1[j] += a1.x*bb.x + a1.y*bb.y + a1.z*bb.z + a1.w*bb.w;
            }
        }
#pragma unroll
        for (int j = 0; j < 4; j++) {
            int g = k0 + tk + 16 * j;
            if (g >= NKV) { s0[j] = -CUDART_INF_F; s1[j] = -CUDART_INF_F; }
            else if (g > 0) {
                int kb = g - 1;
                int kt_ = kb / 49, r2 = kb - kt_ * 49;
                int kh_ = r2 / 7,  kw_ = r2 - kh_ * 7;
                if (qg0 > 0) s0[j] += Eb[tq*22 + kh_] + Eb[tq*22 + 7 + kw_] + Eb[tq*22 + 14 + kt_];
                if (qg1 > 0) s1[j] += Eb[(tq+16)*22 + kh_] + Eb[(tq+16)*22 + 7 + kw_] + Eb[(tq+16)*22 + 14 + kt_];
            }
        }
        {
            float mt = fmaxf(fmaxf(s0[0], s0[1]), fmaxf(s0[2], s0[3]));
#pragma unroll
            for (int off = 8; off; off >>= 1) mt = fmaxf(mt, __shfl_xor_sync(0xffffffffu, mt, off));
            float mn = fmaxf(m0v, mt);
            float alpha = __expf(m0v - mn);
            m0v = mn;
            float ls = 0.f;
#pragma unroll
            for (int j = 0; j < 4; j++) {
                float p = __expf(s0[j] - mn);
                ls += p;
                Ps[tq * 64 + tk + 16 * j] = p;
            }
#pragma unroll
            for (int off = 8; off; off >>= 1) ls += __shfl_xor_sync(0xffffffffu, ls, off);
            l0 = l0 * alpha + ls;
#pragma unroll
            for (int i = 0; i < 6; i++) acc0[i] *= alpha;
        }
        {
            float mt = fmaxf(fmaxf(s1[0], s1[1]), fmaxf(s1[2], s1[3]));
#pragma unroll
            for (int off = 8; off; off >>= 1) mt = fmaxf(mt, __shfl_xor_sync(0xffffffffu, mt, off));
            float mn = fmaxf(m1v, mt);
            float alpha = __expf(m1v - mn);
            m1v = mn;
            float ls = 0.f;
#pragma unroll
            for (int j = 0; j < 4; j++) {
                float p = __expf(s1[j] - mn);
                ls += p;
                Ps[(tq + 16) * 64 + tk + 16 * j] = p;
            }
#pragma unroll
            for (int off = 8; off; off >>= 1) ls += __shfl_xor_sync(0xffffffffu, ls, off);
            l1 = l1 * alpha + ls;
#pragma unroll
            for (int i = 0; i < 6; i++) acc1[i] *= alpha;
        }
        __syncthreads();
        for (int i = t; i < 64 * 24; i += 256) {
            int r = i / 24, c4 = i - r * 24;
            float4 v = (r < nv) ? ld4(vbase + (size_t)(k0 + r) * 96 + c4 * 4)
                                : make_float4(0.f,0.f,0.f,0.f);
            *(float4*)&kv[r * 100 + c4 * 4] = v;
        }
        __syncthreads();
#pragma unroll 4
        for (int k = 0; k < 64; k++) {
            float p0 = Ps[tq * 64 + k];
            float p1 = Ps[(tq + 16) * 64 + k];
            const float2* vr = (const float2*)&kv[k * 100 + tk * 6];
#pragma unroll
            for (int i2 = 0; i2 < 3; i2++) {
                float2 vv = vr[i2];
                acc0[2*i2]   += p0 * vv.x; acc0[2*i2+1] += p0 * vv.y;
                acc1[2*i2]   += p1 * vv.x; acc1[2*i2+1] += p1 * vv.y;
            }
        }
    }

    // epilogue: out/l + residual, write transposed fp16 [B, N, H*HD]
    if (qg0 < NQ) {
        float inv = 1.f / l0;
#pragma unroll
        for (int i = 0; i < 6; i++) {
            int c = tk * 6 + i;
            float val = acc0[i] * inv;
            if (qg0 > 0) val += qbase[(size_t)qg0 * 96 + c];
            g_ao16[((size_t)b * NQ + qg0) * 768 + h * 96 + c] = __float2half(val);
        }
    }
    if (qg1 < NQ) {
        float inv = 1.f / l1;
#pragma unroll
        for (int i = 0; i < 6; i++) {
            int c = tk * 6 + i;
            float val = acc1[i] * inv;
            if (qg1 > 0) val += qbase[(size_t)qg1 * 96 + c];
            g_ao16[((size_t)b * NQ + qg1) * 768 + h * 96 + c] = __float2half(val);
        }
    }
}

// ============================================================
// launch
// ============================================================
extern "C" void kernel_launch(void* const* d_in, const int* in_sizes, int n_in,
                              void* d_out, int out_size)
{
    const float* x      = (const float*)d_in[0];
    const float* qkv_w  = (const float*)d_in[1];
    const float* qkv_b  = (const float*)d_in[2];
    const float* pw_q   = (const float*)d_in[3];
    const float* pw_k   = (const float*)d_in[4];
    const float* pw_v   = (const float*)d_in[5];
    const float* lnq_g  = (const float*)d_in[6];
    const float* lnq_b  = (const float*)d_in[7];
    const float* lnk_g  = (const float*)d_in[8];
    const float* lnk_b  = (const float*)d_in[9];
    const float* lnv_g  = (const float*)d_in[10];
    const float* lnv_b  = (const float*)d_in[11];
    const float* rel_h  = (const float*)d_in[12];
    const float* rel_w  = (const float*)d_in[13];
    const float* rel_t  = (const float*)d_in[14];
    const float* proj_w = (const float*)d_in[15];
    const float* proj_b = (const float*)d_in[16];
    float* out = (float*)d_out;

    // 0. fp16 conversions (x, transposed weights) -> device globals
    conv_x_kernel<<<(MROWS*DIMc/4 + 255)/256, 256>>>(x, MROWS*DIMc/4);
    convT_kernel<<<dim3(72, 24), dim3(32, 8)>>>(qkv_w, 2304, 0);
    convT_kernel<<<dim3(24, 24), dim3(32, 8)>>>(proj_w, 768, 1);
    // 1. fused QKV projection (tensor cores), scattered to [B,H,N,HD] fp32
    gemm16_qkv_kernel<<<dim3(18, 197), 256>>>(qkv_b);
    // 2. attention pooling + LN
    pool_ln_kernel<<<dim3(128, 197), 96>>>(pw_q, lnq_g, lnq_b, 0, 14, 14, 1, 1569);
    pool_ln_kernel<<<dim3(128, 50),  96>>>(pw_k, lnk_g, lnk_b, 1, 7, 7, 2, 393);
    pool_ln_kernel<<<dim3(128, 50),  96>>>(pw_v, lnv_g, lnv_b, 2, 7, 7, 2, 393);
    // 3. decomposed rel-pos bias terms
    ebias_kernel<<<dim3(128, 196), 256>>>(rel_h, rel_w, rel_t);
    // 4. fused attention (writes fp16 transposed output)
    attn_kernel<<<dim3(50, 128), 256>>>();
    // 5. output projection (tensor cores)
    gemm16_proj_kernel<<<dim3(6, 197), 256>>>(proj_b, out);
}

// round 8
// speedup vs baseline: 2.3607x; 1.3818x over previous
#include <cuda_runtime.h>
#include <cuda_fp16.h>
#include <cstdint>
#include <math_constants.h>

// ---------------- problem constants ----------------
constexpr int B_   = 16;
constexpr int NH   = 8;
constexpr int NQ   = 1569;   // 8*14*14 + 1
constexpr int NKV  = 393;    // 8*7*7 + 1
constexpr int HDc  = 96;
constexpr int DIMc = 768;
constexpr int LQ   = 1568;
constexpr int MROWS = B_ * NQ;     // 25104
constexpr int QPAD = 1664;         // 13 * 128
constexpr int KPAD = 448;          // 7 * 64
constexpr float SCALE = 0.10206207261596577f;  // 96^-0.5

// ---------------- scratch (device globals; zero-initialized, no allocs) -----
__device__ float g_q [B_*NH*NQ*HDc];
__device__ float g_k [B_*NH*NQ*HDc];
__device__ float g_v [B_*NH*NQ*HDc];
__device__ float g_qp[B_*NH*NQ*HDc];
__device__ float g_kp[B_*NH*NKV*HDc];
__device__ float g_vp[B_*NH*NKV*HDc];
__device__ float g_E [B_*NH*LQ*22];
__device__ __half g_x16 [MROWS*DIMc];
__device__ __half g_w1T [3*DIMc*DIMc];
__device__ __half g_w2T [DIMc*DIMc];
__device__ __half g_ao16[MROWS*DIMc];
__device__ __half g_qp16[B_*NH*QPAD*HDc];   // pooled q fp16 (unscaled), padded rows zero
__device__ __half g_kp16[B_*NH*KPAD*HDc];   // pooled k fp16 * SCALE, padded rows zero
__device__ __half g_vp16t[B_*NH*HDc*KPAD];  // pooled v fp16 transposed [chan][key], pad zero

__device__ __forceinline__ float4 ld4(const float* p){ return *reinterpret_cast<const float4*>(p); }

// pack two floats -> half2 bits as unsigned (for mma A-fragment)
__device__ __forceinline__ unsigned pack_h2(float lo, float hi)
{
    __half2_raw hr = __floats2half2_rn(lo, hi);
    return (unsigned)hr.x | ((unsigned)hr.y << 16);
}

// ---------------- tensor-core helpers ----------------
__device__ __forceinline__ void ldsm4(unsigned int &r0, unsigned int &r1,
                                      unsigned int &r2, unsigned int &r3,
                                      const __half* p)
{
    unsigned int a = (unsigned int)__cvta_generic_to_shared(p);
    asm volatile("ldmatrix.sync.aligned.m8n8.x4.shared.b16 {%0,%1,%2,%3}, [%4];"
                 : "=r"(r0), "=r"(r1), "=r"(r2), "=r"(r3) : "r"(a));
}
__device__ __forceinline__ void mma16816(float* d, const unsigned int* a, const unsigned int* b)
{
    asm volatile("mma.sync.aligned.m16n8k16.row.col.f32.f16.f16.f32 "
                 "{%0,%1,%2,%3}, {%4,%5,%6,%7}, {%8,%9}, {%0,%1,%2,%3};"
                 : "+f"(d[0]), "+f"(d[1]), "+f"(d[2]), "+f"(d[3])
                 : "r"(a[0]), "r"(a[1]), "r"(a[2]), "r"(a[3]), "r"(b[0]), "r"(b[1]));
}

// ---------------- conversion kernels ----------------
__global__ __launch_bounds__(256) void conv_x_kernel(const float* __restrict__ x, int n4)
{
    int i = blockIdx.x * 256 + threadIdx.x;
    if (i >= n4) return;
    float4 v = reinterpret_cast<const float4*>(x)[i];
    reinterpret_cast<__half2*>(g_x16)[2*i]   = __floats2half2_rn(v.x, v.y);
    reinterpret_cast<__half2*>(g_x16)[2*i+1] = __floats2half2_rn(v.z, v.w);
}

__global__ __launch_bounds__(256) void convT_kernel(const float* __restrict__ w, int N, int which)
{
    __shared__ float tile[32][33];
    __half* wt = which ? g_w2T : g_w1T;
    int n0 = blockIdx.x * 32, k0 = blockIdx.y * 32;
    int tx = threadIdx.x, ty = threadIdx.y;
#pragma unroll
    for (int i = 0; i < 32; i += 8)
        tile[ty + i][tx] = w[(size_t)(k0 + ty + i) * N + n0 + tx];
    __syncthreads();
#pragma unroll
    for (int i = 0; i < 32; i += 8)
        wt[(size_t)(n0 + ty + i) * 768 + k0 + tx] = __float2half(tile[tx][ty + i]);
}

// ============================================================
// fp16 tensor-core GEMM (unchanged from passing round)
// ============================================================
template<int MODE>
__device__ __forceinline__ void gemm16_body(const float* __restrict__ bias, float* __restrict__ C)
{
    __shared__ __half As[2][128*40];
    __shared__ __half Bs[2][128*40];
    const __half* A  = (MODE == 0) ? g_x16 : g_ao16;
    const __half* BT = (MODE == 0) ? g_w1T : g_w2T;
    const int t = threadIdx.x;
    const int n0 = blockIdx.x * 128, m0 = blockIdx.y * 128;
    const int w = t >> 5, lane = t & 31;
    const int wr = w >> 1, wc = w & 1;
    const int arow = t >> 1, aseg = t & 1;

    const __half* Ag = A + (size_t)min(m0 + arow, MROWS - 1) * 768 + aseg * 16;
    const __half* Bg = BT + (size_t)(n0 + arow) * 768 + aseg * 16;

    const int a_m = (lane & 7) + ((lane >> 3) & 1) * 8;
    const int a_k = ((lane >> 4) & 1) * 8;
    const int b_n = (lane & 7) + ((lane >> 4) & 1) * 8;
    const int b_k = ((lane >> 3) & 1) * 8;

    uint4 ra0 = *(const uint4*)Ag;
    uint4 ra1 = *(const uint4*)(Ag + 8);
    uint4 rb0 = *(const uint4*)Bg;
    uint4 rb1 = *(const uint4*)(Bg + 8);
    {
        __half* Ad = &As[0][0] + arow * 40 + aseg * 16;
        *(uint4*)Ad = ra0; *(uint4*)(Ad + 8) = ra1;
        __half* Bd = &Bs[0][0] + arow * 40 + aseg * 16;
        *(uint4*)Bd = rb0; *(uint4*)(Bd + 8) = rb1;
    }
    __syncthreads();

    float acc[2][8][4];
#pragma unroll
    for (int i = 0; i < 2; i++)
#pragma unroll
        for (int j = 0; j < 8; j++)
#pragma unroll
            for (int r = 0; r < 4; r++) acc[i][j][r] = 0.f;

    for (int kt = 0; kt < 24; kt++) {
        const int cur = kt & 1;
        if (kt < 23) {
            const __half* Ap = Ag + (kt + 1) * 32;
            ra0 = *(const uint4*)Ap; ra1 = *(const uint4*)(Ap + 8);
            const __half* Bp = Bg + (kt + 1) * 32;
            rb0 = *(const uint4*)Bp; rb1 = *(const uint4*)(Bp + 8);
        }
        const __half* Ab = &As[cur][0];
        const __half* Bb = &Bs[cur][0];
#pragma unroll
        for (int kk = 0; kk < 32; kk += 16) {
            unsigned int af[2][4];
            ldsm4(af[0][0], af[0][1], af[0][2], af[0][3],
                  Ab + (wr*32 + a_m) * 40 + kk + a_k);
            ldsm4(af[1][0], af[1][1], af[1][2], af[1][3],
                  Ab + (wr*32 + 16 + a_m) * 40 + kk + a_k);
            unsigned int bf[8][2];
#pragma unroll
            for (int nf2 = 0; nf2 < 4; nf2++) {
                unsigned int r0, r1, r2, r3;
                ldsm4(r0, r1, r2, r3, Bb + (wc*64 + nf2*16 + b_n) * 40 + kk + b_k);
                bf[2*nf2][0] = r0; bf[2*nf2][1] = r1;
                bf[2*nf2+1][0] = r2; bf[2*nf2+1][1] = r3;
            }
#pragma unroll
            for (int mf = 0; mf < 2; mf++)
#pragma unroll
                for (int nf = 0; nf < 8; nf++)
                    mma16816(acc[mf][nf], af[mf], bf[nf]);
        }
        if (kt < 23) {
            const int nxt = cur ^ 1;
            __half* Ad = &As[nxt][0] + arow * 40 + aseg * 16;
            *(uint4*)Ad = ra0; *(uint4*)(Ad + 8) = ra1;
            __half* Bd = &Bs[nxt][0] + arow * 40 + aseg * 16;
            *(uint4*)Bd = rb0; *(uint4*)(Bd + 8) = rb1;
            __syncthreads();
        }
    }

    const int mbase = m0 + wr * 32 + (lane >> 2);
    const int nbase = n0 + wc * 64 + (lane & 3) * 2;
#pragma unroll
    for (int mf = 0; mf < 2; mf++) {
#pragma unroll
        for (int nf = 0; nf < 8; nf++) {
            const int n = nbase + nf * 8;
            const float2 bv = *(const float2*)&bias[n];
#pragma unroll
            for (int hh = 0; hh < 2; hh++) {
                const int m = mbase + mf * 16 + hh * 8;
                if (m >= MROWS) continue;
                float2 v2;
                v2.x = acc[mf][nf][2*hh]   + bv.x;
                v2.y = acc[mf][nf][2*hh+1] + bv.y;
                if (MODE == 0) {
                    const int qkvi = n / 768, rem = n - qkvi * 768;
                    const int head = rem / 96, c = rem - head * 96;
                    float* dst = (qkvi == 0) ? g_q : (qkvi == 1) ? g_k : g_v;
                    const int b_ = m / 1569, nn = m - b_ * 1569;
                    *(float2*)&dst[(((size_t)b_*8 + head)*1569 + nn)*96 + c] = v2;
                } else {
                    *(float2*)&C[(size_t)m * 768 + n] = v2;
                }
            }
        }
    }
}

__global__ __launch_bounds__(256) void gemm16_qkv_kernel(const float* __restrict__ bias)
{
    gemm16_body<0>(bias, 0);
}

__global__ __launch_bounds__(256) void gemm16_proj_kernel(const float* __restrict__ bias,
                                                          float* __restrict__ C)
{
    gemm16_body<1>(bias, C);
}

// ============================================================
// Attention pool (depthwise conv3d 3x3x3) + LayerNorm
// Also emits fp16 side outputs for the mma attention.
// ============================================================
__global__ __launch_bounds__(96) void pool_ln_kernel(
    const float* __restrict__ w, const float* __restrict__ gamma, const float* __restrict__ beta,
    int sel, int outH, int outW, int stride, int Nout)
{
    const int bh = blockIdx.x;
    const int c  = threadIdx.x;
    const int lane = c & 31, wid = c >> 5;
    const float* in  = (sel == 0) ? g_q : (sel == 1) ? g_k : g_v;
    float*       out = (sel == 0) ? g_qp : (sel == 1) ? g_kp : g_vp;
    const float* inb  = in  + (size_t)bh * NQ * 96;
    float*       outb = out + (size_t)bh * Nout * 96;

    float wr[27];
#pragma unroll
    for (int i = 0; i < 27; i++) wr[i] = w[c * 27 + i];
    const float gg = gamma[c], bb = beta[c];
    __shared__ float rs[3], rq[3];
    const int HW = outH * outW;

    for (int i = 0; i < 8; i++) {
        int p = blockIdx.y * 8 + i;
        if (p >= Nout) break;
        float val;
        if (p == 0) {
            val = inb[c];
        } else {
            int idx = p - 1;
            int ot = idx / HW, r = idx - ot * HW;
            int oh = r / outW, ow = r - oh * outW;
            val = 0.f;
#pragma unroll
            for (int dt = 0; dt < 3; dt++) {
                int it = ot + dt - 1;
                if ((unsigned)it >= 8u) continue;
#pragma unroll
                for (int dh = 0; dh < 3; dh++) {
                    int ih = oh * stride + dh - 1;
                    if ((unsigned)ih >= 14u) continue;
#pragma unroll
                    for (int dw = 0; dw < 3; dw++) {
                        int iw = ow * stride + dw - 1;
                        if ((unsigned)iw >= 14u) continue;
                        val += inb[(size_t)(1 + (it*14 + ih)*14 + iw)*96 + c] * wr[dt*9 + dh*3 + dw];
                    }
                }
            }
        }
        float s1 = val, s2 = val * val;
#pragma unroll
        for (int off = 16; off; off >>= 1) {
            s1 += __shfl_xor_sync(0xffffffffu, s1, off);
            s2 += __shfl_xor_sync(0xffffffffu, s2, off);
        }
        if (lane == 0) { rs[wid] = s1; rq[wid] = s2; }
        __syncthreads();
        float ts = rs[0] + rs[1] + rs[2];
        float tq = rq[0] + rq[1] + rq[2];
        __syncthreads();
        float mean = ts * (1.f / 96.f);
        float var  = tq * (1.f / 96.f) - mean * mean;
        float nv = (val - mean) * rsqrtf(var + 1e-5f) * gg + bb;
        outb[(size_t)p * 96 + c] = nv;
        if (sel == 0)
            g_qp16[(size_t)bh * QPAD * 96 + (size_t)p * 96 + c] = __float2half(nv);
        else if (sel == 1)
            g_kp16[(size_t)bh * KPAD * 96 + (size_t)p * 96 + c] = __float2half(nv * SCALE);
        else
            g_vp16t[(size_t)bh * 96 * KPAD + (size_t)c * KPAD + p] = __float2half(nv);
    }
}

// ============================================================
// Rel-pos bias decomposition: E[bh, p, 0:7]=q.Rh, [7:14]=q.Rw, [14:22]=q.Rt
// ============================================================
__global__ __launch_bounds__(256) void ebias_kernel(
    const float* __restrict__ rh, const float* __restrict__ rw, const float* __restrict__ rt)
{
    const int bh   = blockIdx.x;
    const int warp = threadIdx.x >> 5, lane = threadIdx.x & 31;
    const int p = blockIdx.y * 8 + warp;
    if (p >= LQ) return;
    const float* q = g_qp + ((size_t)bh * NQ + 1 + p) * 96;
    const float q0 = q[lane], q1 = q[lane + 32], q2 = q[lane + 64];
    const int t = p / 196, r = p - t * 196;
    const int hh = r / 14, ww = r - hh * 14;
    float* Eo = g_E + ((size_t)bh * LQ + p) * 22;

#pragma unroll
    for (int kh = 0; kh < 7; kh++) {
        const float* rr = rh + (hh - 2*kh + 12) * 96;
        float s = q0*rr[lane] + q1*rr[lane+32] + q2*rr[lane+64];
#pragma unroll
        for (int off = 16; off; off >>= 1) s += __shfl_xor_sync(0xffffffffu, s, off);
        if (lane == 0) Eo[kh] = s;
    }
#pragma unroll
    for (int kw = 0; kw < 7; kw++) {
        const float* rr = rw + (ww - 2*kw + 12) * 96;
        float s = q0*rr[lane] + q1*rr[lane+32] + q2*rr[lane+64];
#pragma unroll
        for (int off = 16; off; off >>= 1) s += __shfl_xor_sync(0xffffffffu, s, off);
        if (lane == 0) Eo[7 + kw] = s;
    }
#pragma unroll
    for (int kt = 0; kt < 8; kt++) {
        const float* rr = rt + (t - kt + 7) * 96;
        float s = q0*rr[lane] + q1*rr[lane+32] + q2*rr[lane+64];
#pragma unroll
        for (int off = 16; off; off >>= 1) s += __shfl_xor_sync(0xffffffffu, s, off);
        if (lane == 0) Eo[14 + kt] = s;
    }
}

// ============================================================
// fp16 flash attention: 128 queries x 64-key tiles, 8 warps,
// rel-pos bias from decomposed E, online softmax, AV mma,
// residual + fp16 transposed output.
// ============================================================
__global__ __launch_bounds__(256) void attn16_kernel()
{
    __shared__ __half sbuf[13568];          // K tile [64][104] at 0, Vt tile [96][72] at 6656
    __shared__ float  sEb[128*24];
    __shared__ unsigned sTab[448];

    const int bh = blockIdx.y, b = bh >> 3, h = bh & 7;
    const int q0 = blockIdx.x * 128;
    const int t = threadIdx.x, w = t >> 5, lane = t & 31;
    __half* sK  = sbuf;
    __half* sVt = sbuf + 6656;

    // key decode table: kh | kw<<8 | kt<<16 | valid<<24
    for (int g = t; g < 448; g += 256) {
        unsigned v = 0;
        if (g >= 1 && g < NKV) {
            int kb = g - 1;
            int kt_ = kb / 49, r2 = kb - kt_ * 49;
            int kh_ = r2 / 7,  kw_ = r2 - kh_ * 7;
            v = (unsigned)kh_ | ((unsigned)kw_ << 8) | ((unsigned)kt_ << 16) | (1u << 24);
        }
        sTab[g] = v;
    }
    // per-query bias terms (rows outside body -> 0)
    for (int i = t; i < 128 * 22; i += 256) {
        int q = i / 22, e = i - q * 22;
        int qg = q0 + q;
        sEb[q * 24 + e] = (qg >= 1 && qg < NQ) ? g_E[((size_t)bh * LQ + (qg - 1)) * 22 + e] : 0.f;
    }
    // stage Q tile into sbuf (pitch 104) and load fragments
    const __half* q16b = g_qp16 + (size_t)bh * QPAD * 96;
    for (int i = t; i < 128 * 12; i += 256) {
        int r = i / 12, s = i - r * 12;
        *(uint4*)&sbuf[r * 104 + s * 8] = *(const uint4*)&q16b[(size_t)(q0 + r) * 96 + s * 8];
    }
    __syncthreads();

    const int a_m = (lane & 7) + ((lane >> 3) & 1) * 8;
    const int a_k = ((lane >> 4) & 1) * 8;
    const int b_n = (lane & 7) + ((lane >> 4) & 1) * 8;
    const int b_k = ((lane >> 3) & 1) * 8;

    unsigned aq[6][4];
#pragma unroll
    for (int kk = 0; kk < 6; kk++)
        ldsm4(aq[kk][0], aq[kk][1], aq[kk][2], aq[kk][3],
              &sbuf[(w * 16 + a_m) * 104 + kk * 16 + a_k]);
    __syncthreads();   // Q staging area now reusable for K/Vt

    const int r0 = w * 16 + (lane >> 2);
    const int r1 = r0 + 8;
    const int cbase = (lane & 3) * 2;

    float m0 = -CUDART_INF_F, m1 = -CUDART_INF_F, l0 = 0.f, l1 = 0.f;
    float o[12][4];
#pragma unroll
    for (int i = 0; i < 12; i++)
#pragma unroll
        for (int j = 0; j < 4; j++) o[i][j] = 0.f;

    const __half* k16b = g_kp16 + (size_t)bh * KPAD * 96;
    const __half* v16b = g_vp16t + (size_t)bh * 96 * KPAD;

    for (int k0 = 0; k0 < NKV; k0 += 64) {
        // K tile 64x96 -> pitch 104 ; Vt tile 96x64 -> pitch 72
        for (int i = t; i < 768; i += 256) {
            int r = i / 12, s = i - r * 12;
            *(uint4*)&sK[r * 104 + s * 8] = *(const uint4*)&k16b[(size_t)(k0 + r) * 96 + s * 8];
        }
        for (int i = t; i < 768; i += 256) {
            int r = i / 8, s = i - r * 8;
            *(uint4*)&sVt[r * 72 + s * 8] = *(const uint4*)&v16b[(size_t)r * KPAD + k0 + s * 8];
        }
        __syncthreads();

        // S = Q @ K''^T (scale folded into K)
        float S[8][4];
#pragma unroll
        for (int i = 0; i < 8; i++)
#pragma unroll
            for (int j = 0; j < 4; j++) S[i][j] = 0.f;
#pragma unroll
        for (int kk = 0; kk < 6; kk++) {
            unsigned bf[8][2];
#pragma unroll
            for (int nf2 = 0; nf2 < 4; nf2++) {
                unsigned x0, x1, x2, x3;
                ldsm4(x0, x1, x2, x3, &sK[(nf2 * 16 + b_n) * 104 + kk * 16 + b_k]);
                bf[2*nf2][0] = x0; bf[2*nf2][1] = x1;
                bf[2*nf2+1][0] = x2; bf[2*nf2+1][1] = x3;
            }
#pragma unroll
            for (int nf = 0; nf < 8; nf++)
                mma16816(S[nf], aq[kk], bf[nf]);
        }

        // rel-pos bias + tail mask
#pragma unroll
        for (int nf = 0; nf < 8; nf++) {
            int c0 = cbase + 8 * nf;
            int g0 = k0 + c0, g1 = g0 + 1;
            unsigned t0 = sTab[g0], t1 = sTab[g1];
            if (g0 < NKV) {
                if (t0 >> 24) {
                    int kh_ = t0 & 255, kw_ = (t0 >> 8) & 255, kt_ = (t0 >> 16) & 255;
                    S[nf][0] += sEb[r0*24 + kh_] + sEb[r0*24 + 7 + kw_] + sEb[r0*24 + 14 + kt_];
                    S[nf][2] += sEb[r1*24 + kh_] + sEb[r1*24 + 7 + kw_] + sEb[r1*24 + 14 + kt_];
                }
            } else { S[nf][0] = -CUDART_INF_F; S[nf][2] = -CUDART_INF_F; }
            if (g1 < NKV) {
                if (t1 >> 24) {
                    int kh_ = t1 & 255, kw_ = (t1 >> 8) & 255, kt_ = (t1 >> 16) & 255;
                    S[nf][1] += sEb[r0*24 + kh_] + sEb[r0*24 + 7 + kw_] + sEb[r0*24 + 14 + kt_];
                    S[nf][3] += sEb[r1*24 + kh_] + sEb[r1*24 + 7 + kw_] + sEb[r1*24 + 14 + kt_];
                }
            } else { S[nf][1] = -CUDART_INF_F; S[nf][3] = -CUDART_INF_F; }
        }

        // online softmax (rows r0, r1 per lane; quad holds same rows)
        float mt0 = -CUDART_INF_F, mt1 = -CUDART_INF_F;
#pragma unroll
        for (int nf = 0; nf < 8; nf++) {
            mt0 = fmaxf(mt0, fmaxf(S[nf][0], S[nf][1]));
            mt1 = fmaxf(mt1, fmaxf(S[nf][2], S[nf][3]));
        }
        mt0 = fmaxf(mt0, __shfl_xor_sync(0xffffffffu, mt0, 1));
        mt0 = fmaxf(mt0, __shfl_xor_sync(0xffffffffu, mt0, 2));
        mt1 = fmaxf(mt1, __shfl_xor_sync(0xffffffffu, mt1, 1));
        mt1 = fmaxf(mt1, __shfl_xor_sync(0xffffffffu, mt1, 2));
        float mn0 = fmaxf(m0, mt0), mn1 = fmaxf(m1, mt1);
        float al0 = __expf(m0 - mn0), al1 = __expf(m1 - mn1);
        m0 = mn0; m1 = mn1;

        unsigned ap[4][4];
        float sum0 = 0.f, sum1 = 0.f;
#pragma unroll
        for (int kk = 0; kk < 4; kk++) {
            float p00 = __expf(S[2*kk][0] - m0),   p01 = __expf(S[2*kk][1] - m0);
            float p10 = __expf(S[2*kk][2] - m1),   p11 = __expf(S[2*kk][3] - m1);
            float q00 = __expf(S[2*kk+1][0] - m0), q01 = __expf(S[2*kk+1][1] - m0);
            float q10 = __expf(S[2*kk+1][2] - m1), q11 = __expf(S[2*kk+1][3] - m1);
            sum0 += p00 + p01 + q00 + q01;
            sum1 += p10 + p11 + q10 + q11;
            ap[kk][0] = pack_h2(p00, p01);
            ap[kk][1] = pack_h2(p10, p11);
            ap[kk][2] = pack_h2(q00, q01);
            ap[kk][3] = pack_h2(q10, q11);
        }
        sum0 += __shfl_xor_sync(0xffffffffu, sum0, 1);
        sum0 += __shfl_xor_sync(0xffffffffu, sum0, 2);
        sum1 += __shfl_xor_sync(0xffffffffu, sum1, 1);
        sum1 += __shfl_xor_sync(0xffffffffu, sum1, 2);
        l0 = l0 * al0 + sum0;
        l1 = l1 * al1 + sum1;
#pragma unroll
        for (int nf = 0; nf < 12; nf++) {
            o[nf][0] *= al0; o[nf][1] *= al0;
            o[nf][2] *= al1; o[nf][3] *= al1;
        }

        // O += P @ V
#pragma unroll
        for (int kk = 0; kk < 4; kk++) {
#pragma unroll
            for (int nf2 = 0; nf2 < 6; nf2++) {
                unsigned x0, x1, x2, x3;
                ldsm4(x0, x1, x2, x3, &sVt[(nf2 * 16 + b_n) * 72 + kk * 16 + b_k]);
                unsigned bb0[2] = {x0, x1};
                unsigned bb1[2] = {x2, x3};
                mma16816(o[2*nf2],   ap[kk], bb0);
                mma16816(o[2*nf2+1], ap[kk], bb1);
            }
        }
        __syncthreads();
    }

    // epilogue: /l + residual, write fp16 transposed [B, N, H*96]
    const float inv0 = 1.f / l0, inv1 = 1.f / l1;
    const float* qpb = g_qp + (size_t)bh * NQ * 96;
    const int qg0 = q0 + r0, qg1 = q0 + r1;
    if (qg0 < NQ) {
#pragma unroll
        for (int nf = 0; nf < 12; nf++) {
            int c = cbase + 8 * nf;
            float v0 = o[nf][0] * inv0, v1 = o[nf][1] * inv0;
            if (qg0 > 0) {
                float2 rr = *(const float2*)&qpb[(size_t)qg0 * 96 + c];
                v0 += rr.x; v1 += rr.y;
            }
            *(__half2*)&g_ao16[((size_t)b * NQ + qg0) * 768 + h * 96 + c] = __floats2half2_rn(v0, v1);
        }
    }
    if (qg1 < NQ) {
#pragma unroll
        for (int nf = 0; nf < 12; nf++) {
            int c = cbase + 8 * nf;
            float v0 = o[nf][2] * inv1, v1 = o[nf][3] * inv1;
            if (qg1 > 0) {
                float2 rr = *(const float2*)&qpb[(size_t)qg1 * 96 + c];
                v0 += rr.x; v1 += rr.y;
            }
            *(__half2*)&g_ao16[((size_t)b * NQ + qg1) * 768 + h * 96 + c] = __floats2half2_rn(v0, v1);
        }
    }
}

// ============================================================
// launch
// ============================================================
extern "C" void kernel_launch(void* const* d_in, const int* in_sizes, int n_in,
                              void* d_out, int out_size)
{
    const float* x      = (const float*)d_in[0];
    const float* qkv_w  = (const float*)d_in[1];
    const float* qkv_b  = (const float*)d_in[2];
    const float* pw_q   = (const float*)d_in[3];
    const float* pw_k   = (const float*)d_in[4];
    const float* pw_v   = (const float*)d_in[5];
    const float* lnq_g  = (const float*)d_in[6];
    const float* lnq_b  = (const float*)d_in[7];
    const float* lnk_g  = (const float*)d_in[8];
    const float* lnk_b  = (const float*)d_in[9];
    const float* lnv_g  = (const float*)d_in[10];
    const float* lnv_b  = (const float*)d_in[11];
    const float* rel_h  = (const float*)d_in[12];
    const float* rel_w  = (const float*)d_in[13];
    const float* rel_t  = (const float*)d_in[14];
    const float* proj_w = (const float*)d_in[15];
    const float* proj_b = (const float*)d_in[16];
    float* out = (float*)d_out;

    conv_x_kernel<<<(MROWS*DIMc/4 + 255)/256, 256>>>(x, MROWS*DIMc/4);
    convT_kernel<<<dim3(72, 24), dim3(32, 8)>>>(qkv_w, 2304, 0);
    convT_kernel<<<dim3(24, 24), dim3(32, 8)>>>(proj_w, 768, 1);
    gemm16_qkv_kernel<<<dim3(18, 197), 256>>>(qkv_b);
    pool_ln_kernel<<<dim3(128, 197), 96>>>(pw_q, lnq_g, lnq_b, 0, 14, 14, 1, 1569);
    pool_ln_kernel<<<dim3(128, 50),  96>>>(pw_k, lnk_g, lnk_b, 1, 7, 7, 2, 393);
    pool_ln_kernel<<<dim3(128, 50),  96>>>(pw_v, lnv_g, lnv_b, 2, 7, 7, 2, 393);
    ebias_kernel<<<dim3(128, 196), 256>>>(rel_h, rel_w, rel_t);
    attn16_kernel<<<dim3(13, 128), 256>>>();
    gemm16_proj_kernel<<<dim3(6, 197), 256>>>(proj_b, out);
}

// round 9
// speedup vs baseline: 2.9279x; 1.2403x over previous
#include <cuda_runtime.h>
#include <cuda_fp16.h>
#include <cstdint>
#include <math_constants.h>

// ---------------- problem constants ----------------
constexpr int B_   = 16;
constexpr int NH   = 8;
constexpr int NQ   = 1569;   // 8*14*14 + 1
constexpr int NKV  = 393;    // 8*7*7 + 1
constexpr int HDc  = 96;
constexpr int DIMc = 768;
constexpr int LQ   = 1568;
constexpr int MROWS = B_ * NQ;     // 25104
constexpr int QPAD = 1664;         // 13 * 128
constexpr int KPAD = 448;          // 7 * 64
constexpr float SCALE = 0.10206207261596577f;  // 96^-0.5

// ---------------- scratch (device globals; zero-initialized, no allocs) -----
__device__ float g_q [B_*NH*NQ*HDc];
__device__ float g_k [B_*NH*NQ*HDc];
__device__ float g_v [B_*NH*NQ*HDc];
__device__ float g_qp[B_*NH*NQ*HDc];
__device__ float g_kp[B_*NH*NKV*HDc];
__device__ float g_vp[B_*NH*NKV*HDc];
__device__ float g_E [B_*NH*LQ*22];
__device__ __half g_x16 [MROWS*DIMc];
__device__ __half g_w1T [3*DIMc*DIMc];
__device__ __half g_w2T [DIMc*DIMc];
__device__ __half g_ao16[MROWS*DIMc];
__device__ __half g_qp16[B_*NH*QPAD*HDc];   // pooled q fp16 (unscaled), padded rows zero
__device__ __half g_kp16[B_*NH*KPAD*HDc];   // pooled k fp16 * SCALE, padded rows zero
__device__ __half g_vp16t[B_*NH*HDc*KPAD];  // pooled v fp16 transposed [chan][key], pad zero

__device__ __forceinline__ float4 ld4(const float* p){ return *reinterpret_cast<const float4*>(p); }

// pack two floats -> half2 bits as unsigned (for mma A-fragment)
__device__ __forceinline__ unsigned pack_h2(float lo, float hi)
{
    __half2_raw hr = __floats2half2_rn(lo, hi);
    return (unsigned)hr.x | ((unsigned)hr.y << 16);
}

// ---------------- tensor-core helpers ----------------
__device__ __forceinline__ void ldsm4(unsigned int &r0, unsigned int &r1,
                                      unsigned int &r2, unsigned int &r3,
                                      const __half* p)
{
    unsigned int a = (unsigned int)__cvta_generic_to_shared(p);
    asm volatile("ldmatrix.sync.aligned.m8n8.x4.shared.b16 {%0,%1,%2,%3}, [%4];"
                 : "=r"(r0), "=r"(r1), "=r"(r2), "=r"(r3) : "r"(a));
}
__device__ __forceinline__ void mma16816(float* d, const unsigned int* a, const unsigned int* b)
{
    asm volatile("mma.sync.aligned.m16n8k16.row.col.f32.f16.f16.f32 "
                 "{%0,%1,%2,%3}, {%4,%5,%6,%7}, {%8,%9}, {%0,%1,%2,%3};"
                 : "+f"(d[0]), "+f"(d[1]), "+f"(d[2]), "+f"(d[3])
                 : "r"(a[0]), "r"(a[1]), "r"(a[2]), "r"(a[3]), "r"(b[0]), "r"(b[1]));
}
__device__ __forceinline__ void cpa16(const __half* sdst, const __half* gsrc)
{
    unsigned s = (unsigned)__cvta_generic_to_shared(sdst);
    asm volatile("cp.async.cg.shared.global [%0], [%1], 16;" :: "r"(s), "l"(gsrc));
}

// ---------------- conversion kernels ----------------
__global__ __launch_bounds__(256) void conv_x_kernel(const float* __restrict__ x, int n4)
{
    int i = blockIdx.x * 256 + threadIdx.x;
    if (i >= n4) return;
    float4 v = reinterpret_cast<const float4*>(x)[i];
    reinterpret_cast<__half2*>(g_x16)[2*i]   = __floats2half2_rn(v.x, v.y);
    reinterpret_cast<__half2*>(g_x16)[2*i+1] = __floats2half2_rn(v.z, v.w);
}

__global__ __launch_bounds__(256) void convT_kernel(const float* __restrict__ w, int N, int which)
{
    __shared__ float tile[32][33];
    __half* wt = which ? g_w2T : g_w1T;
    int n0 = blockIdx.x * 32, k0 = blockIdx.y * 32;
    int tx = threadIdx.x, ty = threadIdx.y;
#pragma unroll
    for (int i = 0; i < 32; i += 8)
        tile[ty + i][tx] = w[(size_t)(k0 + ty + i) * N + n0 + tx];
    __syncthreads();
#pragma unroll
    for (int i = 0; i < 32; i += 8)
        wt[(size_t)(n0 + ty + i) * 768 + k0 + tx] = __float2half(tile[tx][ty + i]);
}

// ============================================================
// fp16 tensor-core GEMM: cp.async double-buffered, 2 CTAs/SM
// ============================================================
template<int MODE>
__device__ __forceinline__ void gemm16_body(const float* __restrict__ bias, float* __restrict__ C)
{
    __shared__ __half As[2][128*40];
    __shared__ __half Bs[2][128*40];
    const __half* A  = (MODE == 0) ? g_x16 : g_ao16;
    const __half* BT = (MODE == 0) ? g_w1T : g_w2T;
    const int t = threadIdx.x;
    const int n0 = blockIdx.x * 128, m0 = blockIdx.y * 128;
    const int w = t >> 5, lane = t & 31;
    const int wr = w >> 1, wc = w & 1;
    const int arow = t >> 1, aseg = t & 1;

    const __half* Ag = A + (size_t)min(m0 + arow, MROWS - 1) * 768 + aseg * 16;
    const __half* Bg = BT + (size_t)(n0 + arow) * 768 + aseg * 16;
    __half* Adst = &As[0][0] + arow * 40 + aseg * 16;
    __half* Bdst = &Bs[0][0] + arow * 40 + aseg * 16;

    const int a_m = (lane & 7) + ((lane >> 3) & 1) * 8;
    const int a_k = ((lane >> 4) & 1) * 8;
    const int b_n = (lane & 7) + ((lane >> 4) & 1) * 8;
    const int b_k = ((lane >> 3) & 1) * 8;

    // prologue: stage 0 via cp.async
    cpa16(Adst, Ag);           cpa16(Adst + 8, Ag + 8);
    cpa16(Bdst, Bg);           cpa16(Bdst + 8, Bg + 8);
    asm volatile("cp.async.commit_group;");

    float acc[2][8][4];
#pragma unroll
    for (int i = 0; i < 2; i++)
#pragma unroll
        for (int j = 0; j < 8; j++)
#pragma unroll
            for (int r = 0; r < 4; r++) acc[i][j][r] = 0.f;

    for (int kt = 0; kt < 24; kt++) {
        asm volatile("cp.async.wait_group 0;");
        __syncthreads();
        if (kt < 23) {
            const int nb = (kt + 1) & 1;
            const __half* Ap = Ag + (kt + 1) * 32;
            const __half* Bp = Bg + (kt + 1) * 32;
            __half* Ad = Adst + nb * (128 * 40);
            __half* Bd = Bdst + nb * (128 * 40);
            cpa16(Ad, Ap); cpa16(Ad + 8, Ap + 8);
            cpa16(Bd, Bp); cpa16(Bd + 8, Bp + 8);
            asm volatile("cp.async.commit_group;");
        }
        const __half* Ab = &As[kt & 1][0];
        const __half* Bb = &Bs[kt & 1][0];
#pragma unroll
        for (int kk = 0; kk < 32; kk += 16) {
            unsigned int af[2][4];
            ldsm4(af[0][0], af[0][1], af[0][2], af[0][3],
                  Ab + (wr*32 + a_m) * 40 + kk + a_k);
            ldsm4(af[1][0], af[1][1], af[1][2], af[1][3],
                  Ab + (wr*32 + 16 + a_m) * 40 + kk + a_k);
            unsigned int bf[8][2];
#pragma unroll
            for (int nf2 = 0; nf2 < 4; nf2++) {
                unsigned int r0, r1, r2, r3;
                ldsm4(r0, r1, r2, r3, Bb + (wc*64 + nf2*16 + b_n) * 40 + kk + b_k);
                bf[2*nf2][0] = r0; bf[2*nf2][1] = r1;
                bf[2*nf2+1][0] = r2; bf[2*nf2+1][1] = r3;
            }
#pragma unroll
            for (int mf = 0; mf < 2; mf++)
#pragma unroll
                for (int nf = 0; nf < 8; nf++)
                    mma16816(acc[mf][nf], af[mf], bf[nf]);
        }
    }

    const int mbase = m0 + wr * 32 + (lane >> 2);
    const int nbase = n0 + wc * 64 + (lane & 3) * 2;
#pragma unroll
    for (int mf = 0; mf < 2; mf++) {
#pragma unroll
        for (int nf = 0; nf < 8; nf++) {
            const int n = nbase + nf * 8;
            const float2 bv = *(const float2*)&bias[n];
#pragma unroll
            for (int hh = 0; hh < 2; hh++) {
                const int m = mbase + mf * 16 + hh * 8;
                if (m >= MROWS) continue;
                float2 v2;
                v2.x = acc[mf][nf][2*hh]   + bv.x;
                v2.y = acc[mf][nf][2*hh+1] + bv.y;
                if (MODE == 0) {
                    const int qkvi = n / 768, rem = n - qkvi * 768;
                    const int head = rem / 96, c = rem - head * 96;
                    float* dst = (qkvi == 0) ? g_q : (qkvi == 1) ? g_k : g_v;
                    const int b_ = m / 1569, nn = m - b_ * 1569;
                    *(float2*)&dst[(((size_t)b_*8 + head)*1569 + nn)*96 + c] = v2;
                } else {
                    *(float2*)&C[(size_t)m * 768 + n] = v2;
                }
            }
        }
    }
}

__global__ __launch_bounds__(256, 2) void gemm16_qkv_kernel(const float* __restrict__ bias)
{
    gemm16_body<0>(bias, 0);
}

__global__ __launch_bounds__(256, 2) void gemm16_proj_kernel(const float* __restrict__ bias,
                                                             float* __restrict__ C)
{
    gemm16_body<1>(bias, C);
}

// ============================================================
// Attention pool + LN: warp-per-token, lane owns channels {l, l+32, l+64}.
// No block syncs in the hot path; LN via warp shuffle.
// ============================================================
__global__ __launch_bounds__(256) void pool_ln_kernel(
    const float* __restrict__ w, const float* __restrict__ gamma, const float* __restrict__ beta,
    int sel, int outH, int outW, int stride, int Nout)
{
    __shared__ float sw[96 * 27];
    __shared__ float sg[96], sb[96];
    const int bh = blockIdx.x;
    const int t = threadIdx.x, warp = t >> 5, lane = t & 31;
    for (int i = t; i < 96 * 27; i += 256) sw[i] = w[i];
    if (t < 96) { sg[t] = gamma[t]; sb[t] = beta[t]; }
    __syncthreads();

    const int p = blockIdx.y * 8 + warp;
    if (p >= Nout) return;

    const float* in  = (sel == 0) ? g_q : (sel == 1) ? g_k : g_v;
    float*       out = (sel == 0) ? g_qp : (sel == 1) ? g_kp : g_vp;
    const float* inb  = in  + (size_t)bh * NQ * 96;
    float*       outb = out + (size_t)bh * Nout * 96;

    const int c0 = lane, c1 = lane + 32, c2 = lane + 64;
    float v0 = 0.f, v1 = 0.f, v2 = 0.f;

    if (p == 0) {
        v0 = inb[c0]; v1 = inb[c1]; v2 = inb[c2];
    } else {
        const int HW = outH * outW;
        const int idx = p - 1;
        const int ot = idx / HW, r = idx - ot * HW;
        const int oh = r / outW, ow = r - oh * outW;
#pragma unroll
        for (int dt = 0; dt < 3; dt++) {
            int it = ot + dt - 1;
            if ((unsigned)it >= 8u) continue;
#pragma unroll
            for (int dh = 0; dh < 3; dh++) {
                int ih = oh * stride + dh - 1;
                if ((unsigned)ih >= 14u) continue;
#pragma unroll
                for (int dw = 0; dw < 3; dw++) {
                    int iw = ow * stride + dw - 1;
                    if ((unsigned)iw >= 14u) continue;
                    const float* src = inb + (size_t)(1 + (it*14 + ih)*14 + iw) * 96;
                    const int wi = dt*9 + dh*3 + dw;
                    v0 += src[c0] * sw[c0*27 + wi];
                    v1 += src[c1] * sw[c1*27 + wi];
                    v2 += src[c2] * sw[c2*27 + wi];
                }
            }
        }
    }

    float s1 = v0 + v1 + v2;
    float s2 = v0*v0 + v1*v1 + v2*v2;
#pragma unroll
    for (int off = 16; off; off >>= 1) {
        s1 += __shfl_xor_sync(0xffffffffu, s1, off);
        s2 += __shfl_xor_sync(0xffffffffu, s2, off);
    }
    const float mean = s1 * (1.f / 96.f);
    const float var  = s2 * (1.f / 96.f) - mean * mean;
    const float rstd = rsqrtf(var + 1e-5f);
    const float n0 = (v0 - mean) * rstd * sg[c0] + sb[c0];
    const float n1 = (v1 - mean) * rstd * sg[c1] + sb[c1];
    const float n2 = (v2 - mean) * rstd * sg[c2] + sb[c2];

    outb[(size_t)p * 96 + c0] = n0;
    outb[(size_t)p * 96 + c1] = n1;
    outb[(size_t)p * 96 + c2] = n2;

    if (sel == 0) {
        __half* q16 = g_qp16 + (size_t)bh * QPAD * 96 + (size_t)p * 96;
        q16[c0] = __float2half(n0); q16[c1] = __float2half(n1); q16[c2] = __float2half(n2);
    } else if (sel == 1) {
        __half* k16 = g_kp16 + (size_t)bh * KPAD * 96 + (size_t)p * 96;
        k16[c0] = __float2half(n0 * SCALE); k16[c1] = __float2half(n1 * SCALE); k16[c2] = __float2half(n2 * SCALE);
    } else {
        __half* v16 = g_vp16t + (size_t)bh * 96 * KPAD;
        v16[(size_t)c0 * KPAD + p] = __float2half(n0);
        v16[(size_t)c1 * KPAD + p] = __float2half(n1);
        v16[(size_t)c2 * KPAD + p] = __float2half(n2);
    }
}

// ============================================================
// Rel-pos bias decomposition: E[bh, p, 0:7]=q.Rh, [7:14]=q.Rw, [14:22]=q.Rt
// ============================================================
__global__ __launch_bounds__(256) void ebias_kernel(
    const float* __restrict__ rh, const float* __restrict__ rw, const float* __restrict__ rt)
{
    const int bh   = blockIdx.x;
    const int warp = threadIdx.x >> 5, lane = threadIdx.x & 31;
    const int p = blockIdx.y * 8 + warp;
    if (p >= LQ) return;
    const float* q = g_qp + ((size_t)bh * NQ + 1 + p) * 96;
    const float q0 = q[lane], q1 = q[lane + 32], q2 = q[lane + 64];
    const int t = p / 196, r = p - t * 196;
    const int hh = r / 14, ww = r - hh * 14;
    float* Eo = g_E + ((size_t)bh * LQ + p) * 22;

#pragma unroll
    for (int kh = 0; kh < 7; kh++) {
        const float* rr = rh + (hh - 2*kh + 12) * 96;
        float s = q0*rr[lane] + q1*rr[lane+32] + q2*rr[lane+64];
#pragma unroll
        for (int off = 16; off; off >>= 1) s += __shfl_xor_sync(0xffffffffu, s, off);
        if (lane == 0) Eo[kh] = s;
    }
#pragma unroll
    for (int kw = 0; kw < 7; kw++) {
        const float* rr = rw + (ww - 2*kw + 12) * 96;
        float s = q0*rr[lane] + q1*rr[lane+32] + q2*rr[lane+64];
#pragma unroll
        for (int off = 16; off; off >>= 1) s += __shfl_xor_sync(0xffffffffu, s, off);
        if (lane == 0) Eo[7 + kw] = s;
    }
#pragma unroll
    for (int kt = 0; kt < 8; kt++) {
        const float* rr = rt + (t - kt + 7) * 96;
        float s = q0*rr[lane] + q1*rr[lane+32] + q2*rr[lane+64];
#pragma unroll
        for (int off = 16; off; off >>= 1) s += __shfl_xor_sync(0xffffffffu, s, off);
        if (lane == 0) Eo[14 + kt] = s;
    }
}

// ============================================================
// fp16 flash attention (unchanged from passing round)
// ============================================================
__global__ __launch_bounds__(256) void attn16_kernel()
{
    __shared__ __half sbuf[13568];          // K tile [64][104] at 0, Vt tile [96][72] at 6656
    __shared__ float  sEb[128*24];
    __shared__ unsigned sTab[448];

    const int bh = blockIdx.y, b = bh >> 3, h = bh & 7;
    const int q0 = blockIdx.x * 128;
    const int t = threadIdx.x, w = t >> 5, lane = t & 31;
    __half* sK  = sbuf;
    __half* sVt = sbuf + 6656;

    for (int g = t; g < 448; g += 256) {
        unsigned v = 0;
        if (g >= 1 && g < NKV) {
            int kb = g - 1;
            int kt_ = kb / 49, r2 = kb - kt_ * 49;
            int kh_ = r2 / 7,  kw_ = r2 - kh_ * 7;
            v = (unsigned)kh_ | ((unsigned)kw_ << 8) | ((unsigned)kt_ << 16) | (1u << 24);
        }
        sTab[g] = v;
    }
    for (int i = t; i < 128 * 22; i += 256) {
        int q = i / 22, e = i - q * 22;
        int qg = q0 + q;
        sEb[q * 24 + e] = (qg >= 1 && qg < NQ) ? g_E[((size_t)bh * LQ + (qg - 1)) * 22 + e] : 0.f;
    }
    const __half* q16b = g_qp16 + (size_t)bh * QPAD * 96;
    for (int i = t; i < 128 * 12; i += 256) {
        int r = i / 12, s = i - r * 12;
        *(uint4*)&sbuf[r * 104 + s * 8] = *(const uint4*)&q16b[(size_t)(q0 + r) * 96 + s * 8];
    }
    __syncthreads();

    const int a_m = (lane & 7) + ((lane >> 3) & 1) * 8;
    const int a_k = ((lane >> 4) & 1) * 8;
    const int b_n = (lane & 7) + ((lane >> 4) & 1) * 8;
    const int b_k = ((lane >> 3) & 1) * 8;

    unsigned aq[6][4];
#pragma unroll
    for (int kk = 0; kk < 6; kk++)
        ldsm4(aq[kk][0], aq[kk][1], aq[kk][2], aq[kk][3],
              &sbuf[(w * 16 + a_m) * 104 + kk * 16 + a_k]);
    __syncthreads();

    const int r0 = w * 16 + (lane >> 2);
    const int r1 = r0 + 8;
    const int cbase = (lane & 3) * 2;

    float m0 = -CUDART_INF_F, m1 = -CUDART_INF_F, l0 = 0.f, l1 = 0.f;
    float o[12][4];
#pragma unroll
    for (int i = 0; i < 12; i++)
#pragma unroll
        for (int j = 0; j < 4; j++) o[i][j] = 0.f;

    const __half* k16b = g_kp16 + (size_t)bh * KPAD * 96;
    const __half* v16b = g_vp16t + (size_t)bh * 96 * KPAD;

    for (int k0 = 0; k0 < NKV; k0 += 64) {
        for (int i = t; i < 768; i += 256) {
            int r = i / 12, s = i - r * 12;
            *(uint4*)&sK[r * 104 + s * 8] = *(const uint4*)&k16b[(size_t)(k0 + r) * 96 + s * 8];
        }
        for (int i = t; i < 768; i += 256) {
            int r = i / 8, s = i - r * 8;
            *(uint4*)&sVt[r * 72 + s * 8] = *(const uint4*)&v16b[(size_t)r * KPAD + k0 + s * 8];
        }
        __syncthreads();

        float S[8][4];
#pragma unroll
        for (int i = 0; i < 8; i++)
#pragma unroll
            for (int j = 0; j < 4; j++) S[i][j] = 0.f;
#pragma unroll
        for (int kk = 0; kk < 6; kk++) {
            unsigned bf[8][2];
#pragma unroll
            for (int nf2 = 0; nf2 < 4; nf2++) {
                unsigned x0, x1, x2, x3;
                ldsm4(x0, x1, x2, x3, &sK[(nf2 * 16 + b_n) * 104 + kk * 16 + b_k]);
                bf[2*nf2][0] = x0; bf[2*nf2][1] = x1;
                bf[2*nf2+1][0] = x2; bf[2*nf2+1][1] = x3;
            }
#pragma unroll
            for (int nf = 0; nf < 8; nf++)
                mma16816(S[nf], aq[kk], bf[nf]);
        }

#pragma unroll
        for (int nf = 0; nf < 8; nf++) {
            int c0 = cbase + 8 * nf;
            int g0 = k0 + c0, g1 = g0 + 1;
            unsigned t0 = sTab[g0], t1 = sTab[g1];
            if (g0 < NKV) {
                if (t0 >> 24) {
                    int kh_ = t0 & 255, kw_ = (t0 >> 8) & 255, kt_ = (t0 >> 16) & 255;
                    S[nf][0] += sEb[r0*24 + kh_] + sEb[r0*24 + 7 + kw_] + sEb[r0*24 + 14 + kt_];
                    S[nf][2] += sEb[r1*24 + kh_] + sEb[r1*24 + 7 + kw_] + sEb[r1*24 + 14 + kt_];
                }
            } else { S[nf][0] = -CUDART_INF_F; S[nf][2] = -CUDART_INF_F; }
            if (g1 < NKV) {
                if (t1 >> 24) {
                    int kh_ = t1 & 255, kw_ = (t1 >> 8) & 255, kt_ = (t1 >> 16) & 255;
                    S[nf][1] += sEb[r0*24 + kh_] + sEb[r0*24 + 7 + kw_] + sEb[r0*24 + 14 + kt_];
                    S[nf][3] += sEb[r1*24 + kh_] + sEb[r1*24 + 7 + kw_] + sEb[r1*24 + 14 + kt_];
                }
            } else { S[nf][1] = -CUDART_INF_F; S[nf][3] = -CUDART_INF_F; }
        }

        float mt0 = -CUDART_INF_F, mt1 = -CUDART_INF_F;
#pragma unroll
        for (int nf = 0; nf < 8; nf++) {
            mt0 = fmaxf(mt0, fmaxf(S[nf][0], S[nf][1]));
            mt1 = fmaxf(mt1, fmaxf(S[nf][2], S[nf][3]));
        }
        mt0 = fmaxf(mt0, __shfl_xor_sync(0xffffffffu, mt0, 1));
        mt0 = fmaxf(mt0, __shfl_xor_sync(0xffffffffu, mt0, 2));
        mt1 = fmaxf(mt1, __shfl_xor_sync(0xffffffffu, mt1, 1));
        mt1 = fmaxf(mt1, __shfl_xor_sync(0xffffffffu, mt1, 2));
        float mn0 = fmaxf(m0, mt0), mn1 = fmaxf(m1, mt1);
        float al0 = __expf(m0 - mn0), al1 = __expf(m1 - mn1);
        m0 = mn0; m1 = mn1;

        unsigned ap[4][4];
        float sum0 = 0.f, sum1 = 0.f;
#pragma unroll
        for (int kk = 0; kk < 4; kk++) {
            float p00 = __expf(S[2*kk][0] - m0),   p01 = __expf(S[2*kk][1] - m0);
            float p10 = __expf(S[2*kk][2] - m1),   p11 = __expf(S[2*kk][3] - m1);
            float q00 = __expf(S[2*kk+1][0] - m0), q01 = __expf(S[2*kk+1][1] - m0);
            float q10 = __expf(S[2*kk+1][2] - m1), q11 = __expf(S[2*kk+1][3] - m1);
            sum0 += p00 + p01 + q00 + q01;
            sum1 += p10 + p11 + q10 + q11;
            ap[kk][0] = pack_h2(p00, p01);
            ap[kk][1] = pack_h2(p10, p11);
            ap[kk][2] = pack_h2(q00, q01);
            ap[kk][3] = pack_h2(q10, q11);
        }
        sum0 += __shfl_xor_sync(0xffffffffu, sum0, 1);
        sum0 += __shfl_xor_sync(0xffffffffu, sum0, 2);
        sum1 += __shfl_xor_sync(0xffffffffu, sum1, 1);
        sum1 += __shfl_xor_sync(0xffffffffu, sum1, 2);
        l0 = l0 * al0 + sum0;
        l1 = l1 * al1 + sum1;
#pragma unroll
        for (int nf = 0; nf < 12; nf++) {
            o[nf][0] *= al0; o[nf][1] *= al0;
            o[nf][2] *= al1; o[nf][3] *= al1;
        }

#pragma unroll
        for (int kk = 0; kk < 4; kk++) {
#pragma unroll
            for (int nf2 = 0; nf2 < 6; nf2++) {
                unsigned x0, x1, x2, x3;
                ldsm4(x0, x1, x2, x3, &sVt[(nf2 * 16 + b_n) * 72 + kk * 16 + b_k]);
                unsigned bb0[2] = {x0, x1};
                unsigned bb1[2] = {x2, x3};
                mma16816(o[2*nf2],   ap[kk], bb0);
                mma16816(o[2*nf2+1], ap[kk], bb1);
            }
        }
        __syncthreads();
    }

    const float inv0 = 1.f / l0, inv1 = 1.f / l1;
    const float* qpb = g_qp + (size_t)bh * NQ * 96;
    const int qg0 = q0 + r0, qg1 = q0 + r1;
    if (qg0 < NQ) {
#pragma unroll
        for (int nf = 0; nf < 12; nf++) {
            int c = cbase + 8 * nf;
            float v0 = o[nf][0] * inv0, v1 = o[nf][1] * inv0;
            if (qg0 > 0) {
                float2 rr = *(const float2*)&qpb[(size_t)qg0 * 96 + c];
                v0 += rr.x; v1 += rr.y;
            }
            *(__half2*)&g_ao16[((size_t)b * NQ + qg0) * 768 + h * 96 + c] = __floats2half2_rn(v0, v1);
        }
    }
    if (qg1 < NQ) {
#pragma unroll
        for (int nf = 0; nf < 12; nf++) {
            int c = cbase + 8 * nf;
            float v0 = o[nf][2] * inv1, v1 = o[nf][3] * inv1;
            if (qg1 > 0) {
                float2 rr = *(const float2*)&qpb[(size_t)qg1 * 96 + c];
                v0 += rr.x; v1 += rr.y;
            }
            *(__half2*)&g_ao16[((size_t)b * NQ + qg1) * 768 + h * 96 + c] = __floats2half2_rn(v0, v1);
        }
    }
}

// ============================================================
// launch
// ============================================================
extern "C" void kernel_launch(void* const* d_in, const int* in_sizes, int n_in,
                              void* d_out, int out_size)
{
    const float* x      = (const float*)d_in[0];
    const float* qkv_w  = (const float*)d_in[1];
    const float* qkv_b  = (const float*)d_in[2];
    const float* pw_q   = (const float*)d_in[3];
    const float* pw_k   = (const float*)d_in[4];
    const float* pw_v   = (const float*)d_in[5];
    const float* lnq_g  = (const float*)d_in[6];
    const float* lnq_b  = (const float*)d_in[7];
    const float* lnk_g  = (const float*)d_in[8];
    const float* lnk_b  = (const float*)d_in[9];
    const float* lnv_g  = (const float*)d_in[10];
    const float* lnv_b  = (const float*)d_in[11];
    const float* rel_h  = (const float*)d_in[12];
    const float* rel_w  = (const float*)d_in[13];
    const float* rel_t  = (const float*)d_in[14];
    const float* proj_w = (const float*)d_in[15];
    const float* proj_b = (const float*)d_in[16];
    float* out = (float*)d_out;

    conv_x_kernel<<<(MROWS*DIMc/4 + 255)/256, 256>>>(x, MROWS*DIMc/4);
    convT_kernel<<<dim3(72, 24), dim3(32, 8)>>>(qkv_w, 2304, 0);
    convT_kernel<<<dim3(24, 24), dim3(32, 8)>>>(proj_w, 768, 1);
    gemm16_qkv_kernel<<<dim3(18, 197), 256>>>(qkv_b);
    pool_ln_kernel<<<dim3(128, 197), 256>>>(pw_q, lnq_g, lnq_b, 0, 14, 14, 1, 1569);
    pool_ln_kernel<<<dim3(128, 50),  256>>>(pw_k, lnk_g, lnk_b, 1, 7, 7, 2, 393);
    pool_ln_kernel<<<dim3(128, 50),  256>>>(pw_v, lnv_g, lnv_b, 2, 7, 7, 2, 393);
    ebias_kernel<<<dim3(128, 196), 256>>>(rel_h, rel_w, rel_t);
    attn16_kernel<<<dim3(13, 128), 256>>>();
    gemm16_proj_kernel<<<dim3(6, 197), 256>>>(proj_b, out);
}

// round 11
// speedup vs baseline: 3.7647x; 1.2858x over previous
#include <cuda_runtime.h>
#include <cuda_fp16.h>
#include <cstdint>
#include <math_constants.h>

// ---------------- problem constants ----------------
constexpr int B_   = 16;
constexpr int NH   = 8;
constexpr int NQ   = 1569;   // 8*14*14 + 1
constexpr int NKV  = 393;    // 8*7*7 + 1
constexpr int HDc  = 96;
constexpr int DIMc = 768;
constexpr int LQ   = 1568;
constexpr int MROWS = B_ * NQ;     // 25104
constexpr int QPAD = 1664;         // 13 * 128
constexpr int KPAD = 448;          // 7 * 64
constexpr float SCALE = 0.10206207261596577f;  // 96^-0.5

// ---------------- scratch (device globals; zero-initialized, no allocs) -----
__device__ float g_q [B_*NH*NQ*HDc];
__device__ float g_k [B_*NH*NQ*HDc];
__device__ float g_v [B_*NH*NQ*HDc];
__device__ float g_qp[B_*NH*NQ*HDc];
__device__ float g_kp[B_*NH*NKV*HDc];
__device__ float g_vp[B_*NH*NKV*HDc];
__device__ float g_E [B_*NH*LQ*22];
__device__ __half g_x16 [MROWS*DIMc];
__device__ __half g_w1T [3*DIMc*DIMc];
__device__ __half g_w2T [DIMc*DIMc];
__device__ __half g_ao16[MROWS*DIMc];
__device__ __half g_qp16[B_*NH*QPAD*HDc];   // pooled q fp16 (unscaled), padded rows zero
__device__ __half g_kp16[B_*NH*KPAD*HDc];   // pooled k fp16 * SCALE, padded rows zero
__device__ __half g_vp16t[B_*NH*HDc*KPAD];  // pooled v fp16 transposed [chan][key], pad zero

__device__ __forceinline__ float4 ld4(const float* p){ return *reinterpret_cast<const float4*>(p); }

// pack two floats -> half2 bits as unsigned (for mma A-fragment)
__device__ __forceinline__ unsigned pack_h2(float lo, float hi)
{
    __half2_raw hr = __floats2half2_rn(lo, hi);
    return (unsigned)hr.x | ((unsigned)hr.y << 16);
}

// ---------------- tensor-core helpers ----------------
__device__ __forceinline__ void ldsm4(unsigned int &r0, unsigned int &r1,
                                      unsigned int &r2, unsigned int &r3,
                                      const __half* p)
{
    unsigned int a = (unsigned int)__cvta_generic_to_shared(p);
    asm volatile("ldmatrix.sync.aligned.m8n8.x4.shared.b16 {%0,%1,%2,%3}, [%4];"
                 : "=r"(r0), "=r"(r1), "=r"(r2), "=r"(r3) : "r"(a));
}
__device__ __forceinline__ void mma16816(float* d, const unsigned int* a, const unsigned int* b)
{
    asm volatile("mma.sync.aligned.m16n8k16.row.col.f32.f16.f16.f32 "
                 "{%0,%1,%2,%3}, {%4,%5,%6,%7}, {%8,%9}, {%0,%1,%2,%3};"
                 : "+f"(d[0]), "+f"(d[1]), "+f"(d[2]), "+f"(d[3])
                 : "r"(a[0]), "r"(a[1]), "r"(a[2]), "r"(a[3]), "r"(b[0]), "r"(b[1]));
}
__device__ __forceinline__ void cpa16(const __half* sdst, const __half* gsrc)
{
    unsigned s = (unsigned)__cvta_generic_to_shared(sdst);
    asm volatile("cp.async.cg.shared.global [%0], [%1], 16;" :: "r"(s), "l"(gsrc) : "memory");
}
__device__ __forceinline__ void cpa_commit()
{
    asm volatile("cp.async.commit_group;" ::: "memory");
}

// ---------------- conversion kernels ----------------
__global__ __launch_bounds__(256) void conv_x_kernel(const float* __restrict__ x, int n4)
{
    int i = blockIdx.x * 256 + threadIdx.x;
    if (i >= n4) return;
    float4 v = reinterpret_cast<const float4*>(x)[i];
    reinterpret_cast<__half2*>(g_x16)[2*i]   = __floats2half2_rn(v.x, v.y);
    reinterpret_cast<__half2*>(g_x16)[2*i+1] = __floats2half2_rn(v.z, v.w);
}

__global__ __launch_bounds__(256) void convT_kernel(const float* __restrict__ w, int N, int which)
{
    __shared__ float tile[32][33];
    __half* wt = which ? g_w2T : g_w1T;
    int n0 = blockIdx.x * 32, k0 = blockIdx.y * 32;
    int tx = threadIdx.x, ty = threadIdx.y;
#pragma unroll
    for (int i = 0; i < 32; i += 8)
        tile[ty + i][tx] = w[(size_t)(k0 + ty + i) * N + n0 + tx];
    __syncthreads();
#pragma unroll
    for (int i = 0; i < 32; i += 8)
        wt[(size_t)(n0 + ty + i) * 768 + k0 + tx] = __float2half(tile[tx][ty + i]);
}

// ============================================================
// fp16 tensor-core GEMM: 3-stage cp.async ring (dynamic smem)
// ============================================================
template<int MODE>
__device__ __forceinline__ void gemm16_body(const float* __restrict__ bias, float* __restrict__ C)
{
    extern __shared__ __half dsm[];
    constexpr int STG = 128 * 40;
    const __half* A  = (MODE == 0) ? g_x16 : g_ao16;
    const __half* BT = (MODE == 0) ? g_w1T : g_w2T;
    const int t = threadIdx.x;
    const int n0 = blockIdx.x * 128, m0 = blockIdx.y * 128;
    const int w = t >> 5, lane = t & 31;
    const int wr = w >> 1, wc = w & 1;
    const int arow = t >> 1, aseg = t & 1;

    const __half* Ag = A + (size_t)min(m0 + arow, MROWS - 1) * 768 + aseg * 16;
    const __half* Bg = BT + (size_t)(n0 + arow) * 768 + aseg * 16;
    const int doff = arow * 40 + aseg * 16;

    const int a_m = (lane & 7) + ((lane >> 3) & 1) * 8;
    const int a_k = ((lane >> 4) & 1) * 8;
    const int b_n = (lane & 7) + ((lane >> 4) & 1) * 8;
    const int b_k = ((lane >> 3) & 1) * 8;

    // prologue: stages 0,1 in flight
#pragma unroll
    for (int s = 0; s < 2; s++) {
        __half* Ad = dsm + s * 2 * STG + doff;
        __half* Bd = Ad + STG;
        const __half* Ap = Ag + s * 32;
        const __half* Bp = Bg + s * 32;
        cpa16(Ad, Ap); cpa16(Ad + 8, Ap + 8);
        cpa16(Bd, Bp); cpa16(Bd + 8, Bp + 8);
        cpa_commit();
    }

    float acc[2][8][4];
#pragma unroll
    for (int i = 0; i < 2; i++)
#pragma unroll
        for (int j = 0; j < 8; j++)
#pragma unroll
            for (int r = 0; r < 4; r++) acc[i][j][r] = 0.f;

    for (int kt = 0; kt < 24; kt++) {
        if (kt == 23) asm volatile("cp.async.wait_group 0;" ::: "memory");
        else          asm volatile("cp.async.wait_group 1;" ::: "memory");
        __syncthreads();
        if (kt + 2 < 24) {
            const int s = (kt + 2) % 3;
            __half* Ad = dsm + s * 2 * STG + doff;
            __half* Bd = Ad + STG;
            const __half* Ap = Ag + (kt + 2) * 32;
            const __half* Bp = Bg + (kt + 2) * 32;
            cpa16(Ad, Ap); cpa16(Ad + 8, Ap + 8);
            cpa16(Bd, Bp); cpa16(Bd + 8, Bp + 8);
            cpa_commit();
        }
        const __half* Ab = dsm + (kt % 3) * 2 * STG;
        const __half* Bb = Ab + STG;
#pragma unroll
        for (int kk = 0; kk < 32; kk += 16) {
            unsigned int af[2][4];
            ldsm4(af[0][0], af[0][1], af[0][2], af[0][3],
                  Ab + (wr*32 + a_m) * 40 + kk + a_k);
            ldsm4(af[1][0], af[1][1], af[1][2], af[1][3],
                  Ab + (wr*32 + 16 + a_m) * 40 + kk + a_k);
            unsigned int bf[8][2];
#pragma unroll
            for (int nf2 = 0; nf2 < 4; nf2++) {
                unsigned int r0, r1, r2, r3;
                ldsm4(r0, r1, r2, r3, Bb + (wc*64 + nf2*16 + b_n) * 40 + kk + b_k);
                bf[2*nf2][0] = r0; bf[2*nf2][1] = r1;
                bf[2*nf2+1][0] = r2; bf[2*nf2+1][1] = r3;
            }
#pragma unroll
            for (int mf = 0; mf < 2; mf++)
#pragma unroll
                for (int nf = 0; nf < 8; nf++)
                    mma16816(acc[mf][nf], af[mf], bf[nf]);
        }
    }

    const int mbase = m0 + wr * 32 + (lane >> 2);
    const int nbase = n0 + wc * 64 + (lane & 3) * 2;
#pragma unroll
    for (int mf = 0; mf < 2; mf++) {
#pragma unroll
        for (int nf = 0; nf < 8; nf++) {
            const int n = nbase + nf * 8;
            const float2 bv = *(const float2*)&bias[n];
#pragma unroll
            for (int hh = 0; hh < 2; hh++) {
                const int m = mbase + mf * 16 + hh * 8;
                if (m >= MROWS) continue;
                float2 v2;
                v2.x = acc[mf][nf][2*hh]   + bv.x;
                v2.y = acc[mf][nf][2*hh+1] + bv.y;
                if (MODE == 0) {
                    const int qkvi = n / 768, rem = n - qkvi * 768;
                    const int head = rem / 96, c = rem - head * 96;
                    float* dst = (qkvi == 0) ? g_q : (qkvi == 1) ? g_k : g_v;
                    const int b_ = m / 1569, nn = m - b_ * 1569;
                    *(float2*)&dst[(((size_t)b_*8 + head)*1569 + nn)*96 + c] = v2;
                } else {
                    *(float2*)&C[(size_t)m * 768 + n] = v2;
                }
            }
        }
    }
}

__global__ __launch_bounds__(256, 2) void gemm16_qkv_kernel(const float* __restrict__ bias)
{
    gemm16_body<0>(bias, 0);
}

__global__ __launch_bounds__(256, 2) void gemm16_proj_kernel(const float* __restrict__ bias,
                                                             float* __restrict__ C)
{
    gemm16_body<1>(bias, C);
}

// ============================================================
// Attention pool + LN: warp-per-token (unchanged from passing round)
// ============================================================
__global__ __launch_bounds__(256) void pool_ln_kernel(
    const float* __restrict__ w, const float* __restrict__ gamma, const float* __restrict__ beta,
    int sel, int outH, int outW, int stride, int Nout)
{
    __shared__ float sw[96 * 27];
    __shared__ float sg[96], sb[96];
    const int bh = blockIdx.x;
    const int t = threadIdx.x, warp = t >> 5, lane = t & 31;
    for (int i = t; i < 96 * 27; i += 256) sw[i] = w[i];
    if (t < 96) { sg[t] = gamma[t]; sb[t] = beta[t]; }
    __syncthreads();

    const int p = blockIdx.y * 8 + warp;
    if (p >= Nout) return;

    const float* in  = (sel == 0) ? g_q : (sel == 1) ? g_k : g_v;
    float*       out = (sel == 0) ? g_qp : (sel == 1) ? g_kp : g_vp;
    const float* inb  = in  + (size_t)bh * NQ * 96;
    float*       outb = out + (size_t)bh * Nout * 96;

    const int c0 = lane, c1 = lane + 32, c2 = lane + 64;
    float v0 = 0.f, v1 = 0.f, v2 = 0.f;

    if (p == 0) {
        v0 = inb[c0]; v1 = inb[c1]; v2 = inb[c2];
    } else {
        const int HW = outH * outW;
        const int idx = p - 1;
        const int ot = idx / HW, r = idx - ot * HW;
        const int oh = r / outW, ow = r - oh * outW;
#pragma unroll
        for (int dt = 0; dt < 3; dt++) {
            int it = ot + dt - 1;
            if ((unsigned)it >= 8u) continue;
#pragma unroll
            for (int dh = 0; dh < 3; dh++) {
                int ih = oh * stride + dh - 1;
                if ((unsigned)ih >= 14u) continue;
#pragma unroll
                for (int dw = 0; dw < 3; dw++) {
                    int iw = ow * stride + dw - 1;
                    if ((unsigned)iw >= 14u) continue;
                    const float* src = inb + (size_t)(1 + (it*14 + ih)*14 + iw) * 96;
                    const int wi = dt*9 + dh*3 + dw;
                    v0 += src[c0] * sw[c0*27 + wi];
                    v1 += src[c1] * sw[c1*27 + wi];
                    v2 += src[c2] * sw[c2*27 + wi];
                }
            }
        }
    }

    float s1 = v0 + v1 + v2;
    float s2 = v0*v0 + v1*v1 + v2*v2;
#pragma unroll
    for (int off = 16; off; off >>= 1) {
        s1 += __shfl_xor_sync(0xffffffffu, s1, off);
        s2 += __shfl_xor_sync(0xffffffffu, s2, off);
    }
    const float mean = s1 * (1.f / 96.f);
    const float var  = s2 * (1.f / 96.f) - mean * mean;
    const float rstd = rsqrtf(var + 1e-5f);
    const float n0 = (v0 - mean) * rstd * sg[c0] + sb[c0];
    const float n1 = (v1 - mean) * rstd * sg[c1] + sb[c1];
    const float n2 = (v2 - mean) * rstd * sg[c2] + sb[c2];

    outb[(size_t)p * 96 + c0] = n0;
    outb[(size_t)p * 96 + c1] = n1;
    outb[(size_t)p * 96 + c2] = n2;

    if (sel == 0) {
        __half* q16 = g_qp16 + (size_t)bh * QPAD * 96 + (size_t)p * 96;
        q16[c0] = __float2half(n0); q16[c1] = __float2half(n1); q16[c2] = __float2half(n2);
    } else if (sel == 1) {
        __half* k16 = g_kp16 + (size_t)bh * KPAD * 96 + (size_t)p * 96;
        k16[c0] = __float2half(n0 * SCALE); k16[c1] = __float2half(n1 * SCALE); k16[c2] = __float2half(n2 * SCALE);
    } else {
        __half* v16 = g_vp16t + (size_t)bh * 96 * KPAD;
        v16[(size_t)c0 * KPAD + p] = __float2half(n0);
        v16[(size_t)c1 * KPAD + p] = __float2half(n1);
        v16[(size_t)c2 * KPAD + p] = __float2half(n2);
    }
}

// ============================================================
// Rel-pos bias decomposition (unchanged)
// ============================================================
__global__ __launch_bounds__(256) void ebias_kernel(
    const float* __restrict__ rh, const float* __restrict__ rw, const float* __restrict__ rt)
{
    const int bh   = blockIdx.x;
    const int warp = threadIdx.x >> 5, lane = threadIdx.x & 31;
    const int p = blockIdx.y * 8 + warp;
    if (p >= LQ) return;
    const float* q = g_qp + ((size_t)bh * NQ + 1 + p) * 96;
    const float q0 = q[lane], q1 = q[lane + 32], q2 = q[lane + 64];
    const int t = p / 196, r = p - t * 196;
    const int hh = r / 14, ww = r - hh * 14;
    float* Eo = g_E + ((size_t)bh * LQ + p) * 22;

#pragma unroll
    for (int kh = 0; kh < 7; kh++) {
        const float* rr = rh + (hh - 2*kh + 12) * 96;
        float s = q0*rr[lane] + q1*rr[lane+32] + q2*rr[lane+64];
#pragma unroll
        for (int off = 16; off; off >>= 1) s += __shfl_xor_sync(0xffffffffu, s, off);
        if (lane == 0) Eo[kh] = s;
    }
#pragma unroll
    for (int kw = 0; kw < 7; kw++) {
        const float* rr = rw + (ww - 2*kw + 12) * 96;
        float s = q0*rr[lane] + q1*rr[lane+32] + q2*rr[lane+64];
#pragma unroll
        for (int off = 16; off; off >>= 1) s += __shfl_xor_sync(0xffffffffu, s, off);
        if (lane == 0) Eo[7 + kw] = s;
    }
#pragma unroll
    for (int kt = 0; kt < 8; kt++) {
        const float* rr = rt + (t - kt + 7) * 96;
        float s = q0*rr[lane] + q1*rr[lane+32] + q2*rr[lane+64];
#pragma unroll
        for (int off = 16; off; off >>= 1) s += __shfl_xor_sync(0xffffffffu, s, off);
        if (lane == 0) Eo[14 + kt] = s;
    }
}

// ============================================================
// fp16 flash attention: double-buffered cp.async K/V pipeline.
// Dynamic smem layout (halves): sK[2] at 0 / 6656, sVt[2] at 13312 / 13312+6912.
// ============================================================
__global__ __launch_bounds__(256) void attn16_kernel()
{
    extern __shared__ __half dsm[];
    __shared__ float  sEb[128*24];
    __shared__ unsigned sTab[448];

    const int bh = blockIdx.y, b = bh >> 3, h = bh & 7;
    const int q0 = blockIdx.x * 128;
    const int t = threadIdx.x, w = t >> 5, lane = t & 31;

    for (int g = t; g < 448; g += 256) {
        unsigned v = 0;
        if (g >= 1 && g < NKV) {
            int kb = g - 1;
            int kt_ = kb / 49, r2 = kb - kt_ * 49;
            int kh_ = r2 / 7,  kw_ = r2 - kh_ * 7;
            v = (unsigned)kh_ | ((unsigned)kw_ << 8) | ((unsigned)kt_ << 16) | (1u << 24);
        }
        sTab[g] = v;
    }
    for (int i = t; i < 128 * 22; i += 256) {
        int q = i / 22, e = i - q * 22;
        int qg = q0 + q;
        sEb[q * 24 + e] = (qg >= 1 && qg < NQ) ? g_E[((size_t)bh * LQ + (qg - 1)) * 22 + e] : 0.f;
    }
    // stage Q tile into dsm (pitch 104; fits in the sK area) and load fragments
    const __half* q16b = g_qp16 + (size_t)bh * QPAD * 96;
    for (int i = t; i < 128 * 12; i += 256) {
        int r = i / 12, s = i - r * 12;
        *(uint4*)&dsm[r * 104 + s * 8] = *(const uint4*)&q16b[(size_t)(q0 + r) * 96 + s * 8];
    }
    __syncthreads();

    const int a_m = (lane & 7) + ((lane >> 3) & 1) * 8;
    const int a_k = ((lane >> 4) & 1) * 8;
    const int b_n = (lane & 7) + ((lane >> 4) & 1) * 8;
    const int b_k = ((lane >> 3) & 1) * 8;

    unsigned aq[6][4];
#pragma unroll
    for (int kk = 0; kk < 6; kk++)
        ldsm4(aq[kk][0], aq[kk][1], aq[kk][2], aq[kk][3],
              &dsm[(w * 16 + a_m) * 104 + kk * 16 + a_k]);
    __syncthreads();   // Q reads done; dsm reusable for K/Vt

    const int r0 = w * 16 + (lane >> 2);
    const int r1 = r0 + 8;
    const int cbase = (lane & 3) * 2;

    float m0 = -CUDART_INF_F, m1 = -CUDART_INF_F, l0 = 0.f, l1 = 0.f;
    float o[12][4];
#pragma unroll
    for (int i = 0; i < 12; i++)
#pragma unroll
        for (int j = 0; j < 4; j++) o[i][j] = 0.f;

    const __half* k16b = g_kp16 + (size_t)bh * KPAD * 96;
    const __half* v16b = g_vp16t + (size_t)bh * 96 * KPAD;

    // prologue: tiles 0,1 in flight
#pragma unroll
    for (int pi = 0; pi < 2; pi++) {
        const int k0 = pi * 64;
        __half* sKb  = dsm + pi * 6656;
        __half* sVb  = dsm + 13312 + pi * 6912;
        for (int j = t; j < 1536; j += 256) {
            if (j < 768) {
                int r = j / 12, c = j - r * 12;
                cpa16(sKb + r * 104 + c * 8, k16b + (size_t)(k0 + r) * 96 + c * 8);
            } else {
                int q = j - 768; int r = q >> 3, c = q & 7;
                cpa16(sVb + r * 72 + c * 8, v16b + (size_t)r * KPAD + k0 + c * 8);
            }
        }
        cpa_commit();
    }

    for (int i = 0; i < 7; i++) {
        if (i == 6) asm volatile("cp.async.wait_group 0;" ::: "memory");
        else        asm volatile("cp.async.wait_group 1;" ::: "memory");
        __syncthreads();
        const int bf = i & 1;
        const __half* sK  = dsm + bf * 6656;
        const __half* sVt = dsm + 13312 + bf * 6912;
        const int k0 = i * 64;

        float S[8][4];
#pragma unroll
        for (int ii = 0; ii < 8; ii++)
#pragma unroll
            for (int j = 0; j < 4; j++) S[ii][j] = 0.f;
#pragma unroll
        for (int kk = 0; kk < 6; kk++) {
            unsigned bfr[8][2];
#pragma unroll
            for (int nf2 = 0; nf2 < 4; nf2++) {
                unsigned x0, x1, x2, x3;
                ldsm4(x0, x1, x2, x3, &sK[(nf2 * 16 + b_n) * 104 + kk * 16 + b_k]);
                bfr[2*nf2][0] = x0; bfr[2*nf2][1] = x1;
                bfr[2*nf2+1][0] = x2; bfr[2*nf2+1][1] = x3;
            }
#pragma unroll
            for (int nf = 0; nf < 8; nf++)
                mma16816(S[nf], aq[kk], bfr[nf]);
        }

#pragma unroll
        for (int nf = 0; nf < 8; nf++) {
            int c0 = cbase + 8 * nf;
            int g0 = k0 + c0, g1 = g0 + 1;
            unsigned t0 = sTab[g0], t1 = sTab[g1];
            if (g0 < NKV) {
                if (t0 >> 24) {
                    int kh_ = t0 & 255, kw_ = (t0 >> 8) & 255, kt_ = (t0 >> 16) & 255;
                    S[nf][0] += sEb[r0*24 + kh_] + sEb[r0*24 + 7 + kw_] + sEb[r0*24 + 14 + kt_];
                    S[nf][2] += sEb[r1*24 + kh_] + sEb[r1*24 + 7 + kw_] + sEb[r1*24 + 14 + kt_];
                }
            } else { S[nf][0] = -CUDART_INF_F; S[nf][2] = -CUDART_INF_F; }
            if (g1 < NKV) {
                if (t1 >> 24) {
                    int kh_ = t1 & 255, kw_ = (t1 >> 8) & 255, kt_ = (t1 >> 16) & 255;
                    S[nf][1] += sEb[r0*24 + kh_] + sEb[r0*24 + 7 + kw_] + sEb[r0*24 + 14 + kt_];
                    S[nf][3] += sEb[r1*24 + kh_] + sEb[r1*24 + 7 + kw_] + sEb[r1*24 + 14 + kt_];
                }
            } else { S[nf][1] = -CUDART_INF_F; S[nf][3] = -CUDART_INF_F; }
        }

        float mt0 = -CUDART_INF_F, mt1 = -CUDART_INF_F;
#pragma unroll
        for (int nf = 0; nf < 8; nf++) {
            mt0 = fmaxf(mt0, fmaxf(S[nf][0], S[nf][1]));
            mt1 = fmaxf(mt1, fmaxf(S[nf][2], S[nf][3]));
        }
        mt0 = fmaxf(mt0, __shfl_xor_sync(0xffffffffu, mt0, 1));
        mt0 = fmaxf(mt0, __shfl_xor_sync(0xffffffffu, mt0, 2));
        mt1 = fmaxf(mt1, __shfl_xor_sync(0xffffffffu, mt1, 1));
        mt1 = fmaxf(mt1, __shfl_xor_sync(0xffffffffu, mt1, 2));
        float mn0 = fmaxf(m0, mt0), mn1 = fmaxf(m1, mt1);
        float al0 = __expf(m0 - mn0), al1 = __expf(m1 - mn1);
        m0 = mn0; m1 = mn1;

        unsigned ap[4][4];
        float sum0 = 0.f, sum1 = 0.f;
#pragma unroll
        for (int kk = 0; kk < 4; kk++) {
            float p00 = __expf(S[2*kk][0] - m0),   p01 = __expf(S[2*kk][1] - m0);
            float p10 = __expf(S[2*kk][2] - m1),   p11 = __expf(S[2*kk][3] - m1);
            float q00 = __expf(S[2*kk+1][0] - m0), q01 = __expf(S[2*kk+1][1] - m0);
            float q10 = __expf(S[2*kk+1][2] - m1), q11 = __expf(S[2*kk+1][3] - m1);
            sum0 += p00 + p01 + q00 + q01;
            sum1 += p10 + p11 + q10 + q11;
            ap[kk][0] = pack_h2(p00, p01);
            ap[kk][1] = pack_h2(p10, p11);
            ap[kk][2] = pack_h2(q00, q01);
            ap[kk][3] = pack_h2(q10, q11);
        }
        sum0 += __shfl_xor_sync(0xffffffffu, sum0, 1);
        sum0 += __shfl_xor_sync(0xffffffffu, sum0, 2);
        sum1 += __shfl_xor_sync(0xffffffffu, sum1, 1);
        sum1 += __shfl_xor_sync(0xffffffffu, sum1, 2);
        l0 = l0 * al0 + sum0;
        l1 = l1 * al1 + sum1;
#pragma unroll
        for (int nf = 0; nf < 12; nf++) {
            o[nf][0] *= al0; o[nf][1] *= al0;
            o[nf][2] *= al1; o[nf][3] *= al1;
        }

#pragma unroll
        for (int kk = 0; kk < 4; kk++) {
#pragma unroll
            for (int nf2 = 0; nf2 < 6; nf2++) {
                unsigned x0, x1, x2, x3;
                ldsm4(x0, x1, x2, x3, &sVt[(nf2 * 16 + b_n) * 72 + kk * 16 + b_k]);
                unsigned bb0[2] = {x0, x1};
                unsigned bb1[2] = {x2, x3};
                mma16816(o[2*nf2],   ap[kk], bb0);
                mma16816(o[2*nf2+1], ap[kk], bb1);
            }
        }
        __syncthreads();   // all warps done with buffer bf

        if (i + 2 < 7) {
            const int k0n = (i + 2) * 64;
            __half* sKb = dsm + bf * 6656;
            __half* sVb = dsm + 13312 + bf * 6912;
            for (int j = t; j < 1536; j += 256) {
                if (j < 768) {
                    int r = j / 12, c = j - r * 12;
                    cpa16(sKb + r * 104 + c * 8, k16b + (size_t)(k0n + r) * 96 + c * 8);
                } else {
                    int q = j - 768; int r = q >> 3, c = q & 7;
                    cpa16(sVb + r * 72 + c * 8, v16b + (size_t)r * KPAD + k0n + c * 8);
                }
            }
            cpa_commit();
        }
    }

    const float inv0 = 1.f / l0, inv1 = 1.f / l1;
    const float* qpb = g_qp + (size_t)bh * NQ * 96;
    const int qg0 = q0 + r0, qg1 = q0 + r1;
    if (qg0 < NQ) {
#pragma unroll
        for (int nf = 0; nf < 12; nf++) {
            int c = cbase + 8 * nf;
            float v0 = o[nf][0] * inv0, v1 = o[nf][1] * inv0;
            if (qg0 > 0) {
                float2 rr = *(const float2*)&qpb[(size_t)qg0 * 96 + c];
                v0 += rr.x; v1 += rr.y;
            }
            *(__half2*)&g_ao16[((size_t)b * NQ + qg0) * 768 + h * 96 + c] = __floats2half2_rn(v0, v1);
        }
    }
    if (qg1 < NQ) {
#pragma unroll
        for (int nf = 0; nf < 12; nf++) {
            int c = cbase + 8 * nf;
            float v0 = o[nf][2] * inv1, v1 = o[nf][3] * inv1;
            if (qg1 > 0) {
                float2 rr = *(const float2*)&qpb[(size_t)qg1 * 96 + c];
                v0 += rr.x; v1 += rr.y;
            }
            *(__half2*)&g_ao16[((size_t)b * NQ + qg1) * 768 + h * 96 + c] = __floats2half2_rn(v0, v1);
        }
    }
}

// ============================================================
// launch
// ============================================================
extern "C" void kernel_launch(void* const* d_in, const int* in_sizes, int n_in,
                              void* d_out, int out_size)
{
    const float* x      = (const float*)d_in[0];
    const float* qkv_w  = (const float*)d_in[1];
    const float* qkv_b  = (const float*)d_in[2];
    const float* pw_q   = (const float*)d_in[3];
    const float* pw_k   = (const float*)d_in[4];
    const float* pw_v   = (const float*)d_in[5];
    const float* lnq_g  = (const float*)d_in[6];
    const float* lnq_b  = (const float*)d_in[7];
    const float* lnk_g  = (const float*)d_in[8];
    const float* lnk_b  = (const float*)d_in[9];
    const float* lnv_g  = (const float*)d_in[10];
    const float* lnv_b  = (const float*)d_in[11];
    const float* rel_h  = (const float*)d_in[12];
    const float* rel_w  = (const float*)d_in[13];
    const float* rel_t  = (const float*)d_in[14];
    const float* proj_w = (const float*)d_in[15];
    const float* proj_b = (const float*)d_in[16];
    float* out = (float*)d_out;

    const int gemm_smem = 3 * 2 * 128 * 40 * (int)sizeof(__half);   // 61440
    const int attn_smem = (13312 + 13824) * (int)sizeof(__half);    // 54272
    cudaFuncSetAttribute(gemm16_qkv_kernel,  cudaFuncAttributeMaxDynamicSharedMemorySize, gemm_smem);
    cudaFuncSetAttribute(gemm16_proj_kernel, cudaFuncAttributeMaxDynamicSharedMemorySize, gemm_smem);
    cudaFuncSetAttribute(attn16_kernel,      cudaFuncAttributeMaxDynamicSharedMemorySize, attn_smem);

    conv_x_kernel<<<(MROWS*DIMc/4 + 255)/256, 256>>>(x, MROWS*DIMc/4);
    convT_kernel<<<dim3(72, 24), dim3(32, 8)>>>(qkv_w, 2304, 0);
    convT_kernel<<<dim3(24, 24), dim3(32, 8)>>>(proj_w, 768, 1);
    gemm16_qkv_kernel<<<dim3(18, 197), 256, gemm_smem>>>(qkv_b);
    pool_ln_kernel<<<dim3(128, 197), 256>>>(pw_q, lnq_g, lnq_b, 0, 14, 14, 1, 1569);
    pool_ln_kernel<<<dim3(128, 50),  256>>>(pw_k, lnk_g, lnk_b, 1, 7, 7, 2, 393);
    pool_ln_kernel<<<dim3(128, 50),  256>>>(pw_v, lnv_g, lnv_b, 2, 7, 7, 2, 393);
    ebias_kernel<<<dim3(128, 196), 256>>>(rel_h, rel_w, rel_t);
    attn16_kernel<<<dim3(13, 128), 256, attn_smem>>>();
    gemm16_proj_kernel<<<dim3(6, 197), 256, gemm_smem>>>(proj_b, out);
}